// round 12
// baseline (speedup 1.0000x reference)
#include <cuda_runtime.h>
#include <cstdint>
#include <math.h>

#define Bb 32
#define Nn 197
#define Cc 768
#define Hh 12
#define Dd 64
#define NN (Nn*Nn)      // 38809
#define BH (Bb*Hh)      // 384
#define M1 (Bb*Nn)      // 6304
#define NNP 224         // padded attnW row stride (7*32, 16B aligned)
#define SCALE 0.125f

// ---------------- scratch (no allocations allowed) ----------------
__device__ float g_q[BH*Nn*Dd];      // [B,H,N,D]
__device__ float g_k[BH*Nn*Dd];
__device__ float g_v[BH*Nn*Dd];
__device__ float g_attnW[(size_t)BH*Nn*NNP];   // conv_w-mixed probs, padded rows (pads stay 0)
__device__ float g_oh[(size_t)M1*Cc];          // out heads, [B,N,C] pre-proj

// ---------------- warp reductions ----------------
__device__ __forceinline__ float warpMax(float v){
#pragma unroll
    for (int o=16;o>0;o>>=1) v = fmaxf(v, __shfl_xor_sync(0xffffffffu, v, o));
    return v;
}
__device__ __forceinline__ float warpSum(float v){
#pragma unroll
    for (int o=16;o>0;o>>=1) v += __shfl_xor_sync(0xffffffffu, v, o);
    return v;
}

// ---------------- tf32 helpers ----------------
__device__ __forceinline__ uint32_t f2tf32(float x) {
    uint32_t u;
    asm("cvt.rna.tf32.f32 %0, %1;" : "=r"(u) : "f"(x));
    return u;
}
__device__ __forceinline__ void mma_tf32(float* d,
                                         uint32_t a0, uint32_t a1, uint32_t a2, uint32_t a3,
                                         uint32_t b0, uint32_t b1) {
    asm volatile(
        "mma.sync.aligned.m16n8k8.row.col.f32.tf32.tf32.f32 "
        "{%0,%1,%2,%3}, {%4,%5,%6,%7}, {%8,%9}, {%0,%1,%2,%3};"
        : "+f"(d[0]), "+f"(d[1]), "+f"(d[2]), "+f"(d[3])
        : "r"(a0), "r"(a1), "r"(a2), "r"(a3), "r"(b0), "r"(b1));
}

#define TGP2 20                   // smem row stride (chunk 16 + pad 4)

// =====================================================================
// K1/K6: dense GEMM, double-buffered pipeline. C[M,N] = A[M,K] @ B[K,N]
// block 128x128, K-chunk 16, 8 warps (2m x 4n).
// mode 0: A=x, qkv scatter. mode 1: A=g_oh (device symbol), proj+bias.
// =====================================================================
__global__ __launch_bounds__(256) void k_tgemm(const float* __restrict__ A_ext, int lda,
                                               const float* __restrict__ B, int ldb,
                                               int Ktot, int mode,
                                               const float* __restrict__ bias,
                                               float* __restrict__ out)
{
    __shared__ __align__(16) float shA[2][128*TGP2];
    __shared__ __align__(16) float shB[2][128*TGP2];

    const float* A = (mode == 1) ? g_oh : A_ext;

    const int tid  = threadIdx.x;
    const int wid  = tid >> 5, lane = tid & 31;
    const int gid  = lane >> 2, tig = lane & 3;
    const int warp_m = (wid >> 2) * 64;
    const int warp_n = (wid & 3) * 32;
    const int row0 = blockIdx.y * 128;
    const int col0 = blockIdx.x * 128;

    float acc[4][4][4] = {};
    const int nchunks = Ktot >> 4;

    auto stage = [&](int c, int buf) {
        const int k0 = c << 4;
#pragma unroll
        for (int it = 0; it < 2; it++) {
            int e = it * 256 + tid;            // 0..511
            int r = e >> 2, k4 = (e & 3) * 4;
            int gr = row0 + r;
            float4 x = make_float4(0.f,0.f,0.f,0.f);
            if (gr < M1) x = *(const float4*)&A[(size_t)gr * lda + k0 + k4];
            float4 t;
            t.x = __uint_as_float(f2tf32(x.x));
            t.y = __uint_as_float(f2tf32(x.y));
            t.z = __uint_as_float(f2tf32(x.z));
            t.w = __uint_as_float(f2tf32(x.w));
            *(float4*)&shA[buf][r*TGP2 + k4] = t;
        }
#pragma unroll
        for (int it = 0; it < 2; it++) {
            int e = it * 256 + tid;
            int k = e >> 5, n4 = (e & 31) * 4;
            float4 x = *(const float4*)&B[(size_t)(k0 + k) * ldb + col0 + n4];
            shB[buf][(n4+0)*TGP2 + k] = __uint_as_float(f2tf32(x.x));
            shB[buf][(n4+1)*TGP2 + k] = __uint_as_float(f2tf32(x.y));
            shB[buf][(n4+2)*TGP2 + k] = __uint_as_float(f2tf32(x.z));
            shB[buf][(n4+3)*TGP2 + k] = __uint_as_float(f2tf32(x.w));
        }
    };

    stage(0, 0);
    __syncthreads();

    for (int c = 0; c < nchunks; c++) {
        const int buf = c & 1;
        if (c + 1 < nchunks) stage(c + 1, buf ^ 1);
#pragma unroll
        for (int ks = 0; ks < 2; ks++) {
            const int kk = ks * 8;
            uint32_t ah[4][4];
#pragma unroll
            for (int ma = 0; ma < 4; ma++) {
                int r = warp_m + ma*16 + gid;
                const float* ph = &shA[buf][r*TGP2 + kk + tig];
                ah[ma][0] = __float_as_uint(ph[0]);
                ah[ma][1] = __float_as_uint(ph[8*TGP2]);
                ah[ma][2] = __float_as_uint(ph[4]);
                ah[ma][3] = __float_as_uint(ph[8*TGP2 + 4]);
            }
#pragma unroll
            for (int na = 0; na < 4; na++) {
                int cn = warp_n + na*8 + gid;
                uint32_t b0 = __float_as_uint(shB[buf][cn*TGP2 + kk + tig]);
                uint32_t b1 = __float_as_uint(shB[buf][cn*TGP2 + kk + tig + 4]);
#pragma unroll
                for (int ma = 0; ma < 4; ma++)
                    mma_tf32(acc[ma][na], ah[ma][0], ah[ma][1], ah[ma][2], ah[ma][3], b0, b1);
            }
        }
        __syncthreads();
    }

#pragma unroll
    for (int ma = 0; ma < 4; ma++) {
#pragma unroll
        for (int na = 0; na < 4; na++) {
            int colg = col0 + warp_n + na*8 + 2*tig;
#pragma unroll
            for (int half = 0; half < 2; half++) {
                int row = row0 + warp_m + ma*16 + gid + half*8;
                if (row >= M1) continue;
                float v0 = acc[ma][na][half*2 + 0];
                float v1 = acc[ma][na][half*2 + 1];
                if (mode == 0) {
                    int t = colg / 768;
                    int rem = colg - t*768;
                    int h = rem >> 6, d0 = rem & 63;
                    float* dst = (t==0) ? g_q : (t==1) ? g_k : g_v;
                    int b = row / Nn, n = row - b*Nn;
                    float* p = dst + ((size_t)(b*Hh + h)*Nn + n)*Dd + d0;
                    p[0] = v0; p[1] = v1;
                } else {
                    float* p = out + (size_t)row*768 + colg;
                    p[0] = v0 + bias[colg];
                    p[1] = v1 + bias[colg + 1];
                }
            }
        }
    }
}

// =====================================================================
// K2: batched NT GEMM, double-buffered: out[z,n,m] = alpha*sum_d A*B
// block 128x128, K=64 (4 chunks of 16), 8 warps (2m x 4n).
// =====================================================================
__global__ __launch_bounds__(256) void k_bgemm_tf32(int mode,
                                                    float* __restrict__ out,
                                                    float alpha)
{
    __shared__ __align__(16) float shA[2][128*TGP2];
    __shared__ __align__(16) float shB[2][128*TGP2];

    const int z = blockIdx.z;
    const float* Az = (mode==0 ? g_q : g_v) + (size_t)z*Nn*Dd;
    const float* Bz = (mode==0 ? g_k : g_v) + (size_t)z*Nn*Dd;
    float* Oz = out + (size_t)z*NN;

    const int tid  = threadIdx.x;
    const int wid  = tid >> 5, lane = tid & 31;
    const int gid  = lane >> 2, tig = lane & 3;
    const int warp_m = (wid >> 2) * 64;
    const int warp_n = (wid & 3) * 32;
    const int n0 = blockIdx.y * 128;
    const int m0 = blockIdx.x * 128;

    float acc[4][4][4] = {};

    auto stage = [&](int c, int buf) {
        const int k0 = c << 4;
#pragma unroll
        for (int it = 0; it < 2; it++) {
            int e = it * 256 + tid;
            int r = e >> 2, k4 = (e & 3) * 4;
            int ga = n0 + r, gb = m0 + r;
            float4 xa = make_float4(0.f,0.f,0.f,0.f);
            float4 xb = make_float4(0.f,0.f,0.f,0.f);
            if (ga < Nn) xa = *(const float4*)&Az[(size_t)ga*Dd + k0 + k4];
            if (gb < Nn) xb = *(const float4*)&Bz[(size_t)gb*Dd + k0 + k4];
            float4 ta, tb;
            ta.x=__uint_as_float(f2tf32(xa.x)); ta.y=__uint_as_float(f2tf32(xa.y));
            ta.z=__uint_as_float(f2tf32(xa.z)); ta.w=__uint_as_float(f2tf32(xa.w));
            tb.x=__uint_as_float(f2tf32(xb.x)); tb.y=__uint_as_float(f2tf32(xb.y));
            tb.z=__uint_as_float(f2tf32(xb.z)); tb.w=__uint_as_float(f2tf32(xb.w));
            *(float4*)&shA[buf][r*TGP2 + k4] = ta;
            *(float4*)&shB[buf][r*TGP2 + k4] = tb;
        }
    };

    stage(0, 0);
    __syncthreads();

    for (int c = 0; c < 4; c++) {
        const int buf = c & 1;
        if (c + 1 < 4) stage(c + 1, buf ^ 1);
#pragma unroll
        for (int ks = 0; ks < 2; ks++) {
            const int kk = ks * 8;
            uint32_t ah[4][4];
#pragma unroll
            for (int ma = 0; ma < 4; ma++) {
                int r = warp_m + ma*16 + gid;
                const float* ph = &shA[buf][r*TGP2 + kk + tig];
                ah[ma][0] = __float_as_uint(ph[0]);
                ah[ma][1] = __float_as_uint(ph[8*TGP2]);
                ah[ma][2] = __float_as_uint(ph[4]);
                ah[ma][3] = __float_as_uint(ph[8*TGP2 + 4]);
            }
#pragma unroll
            for (int na = 0; na < 4; na++) {
                int cn = warp_n + na*8 + gid;
                uint32_t b0 = __float_as_uint(shB[buf][cn*TGP2 + kk + tig]);
                uint32_t b1 = __float_as_uint(shB[buf][cn*TGP2 + kk + tig + 4]);
#pragma unroll
                for (int ma = 0; ma < 4; ma++)
                    mma_tf32(acc[ma][na], ah[ma][0], ah[ma][1], ah[ma][2], ah[ma][3], b0, b1);
            }
        }
        __syncthreads();
    }

#pragma unroll
    for (int ma = 0; ma < 4; ma++) {
#pragma unroll
        for (int na = 0; na < 4; na++) {
            int mg = m0 + warp_n + na*8 + 2*tig;
#pragma unroll
            for (int half = 0; half < 2; half++) {
                int n = n0 + warp_m + ma*16 + gid + half*8;
                if (n >= Nn) continue;
                if (mg < Nn)     Oz[(size_t)n*Nn + mg]     = alpha*acc[ma][na][half*2+0];
                if (mg + 1 < Nn) Oz[(size_t)n*Nn + mg + 1] = alpha*acc[ma][na][half*2+1];
            }
        }
    }
}

// =====================================================================
// K5: av, double-buffered: out[n,d] = sum_m attnW[n,m] * v[m,d]
// attnW rows padded to NNP=224 (pads exact zero). 14 chunks of 16.
// block 128x64, 8 warps (4m x 2n).
// =====================================================================
__global__ __launch_bounds__(256) void k_av_tf32()
{
    __shared__ __align__(16) float shA[2][128*TGP2];   // [n][k]
    __shared__ __align__(16) float shB[2][64*TGP2];    // [d][k]

    const int z = blockIdx.z;
    const int b = z / Hh, h = z - b*Hh;
    const float* Az = g_attnW + (size_t)z*Nn*NNP;
    const float* Vz = g_v + (size_t)z*Nn*Dd;

    const int tid  = threadIdx.x;
    const int wid  = tid >> 5, lane = tid & 31;
    const int gid  = lane >> 2, tig = lane & 3;
    const int warp_m = (wid >> 1) * 32;
    const int warp_n = (wid & 1) * 32;
    const int n0 = blockIdx.y * 128;

    float acc[2][4][4] = {};

    auto stage = [&](int c, int buf) {
        const int k0 = c << 4;
#pragma unroll
        for (int it = 0; it < 2; it++) {
            int e = it * 256 + tid;
            int r = e >> 2, k4 = (e & 3) * 4;
            int gr = n0 + r;
            float4 x = make_float4(0.f,0.f,0.f,0.f);
            if (gr < Nn) x = *(const float4*)&Az[(size_t)gr*NNP + k0 + k4];
            float4 t;
            t.x=__uint_as_float(f2tf32(x.x)); t.y=__uint_as_float(f2tf32(x.y));
            t.z=__uint_as_float(f2tf32(x.z)); t.w=__uint_as_float(f2tf32(x.w));
            *(float4*)&shA[buf][r*TGP2 + k4] = t;
        }
        {
            int e = tid;                       // 256 float4 covers 16k x 64d
            int k = e >> 4, n4 = (e & 15) * 4;
            float4 x = make_float4(0.f,0.f,0.f,0.f);
            if (k0 + k < Nn) x = *(const float4*)&Vz[(size_t)(k0 + k)*Dd + n4];
            shB[buf][(n4+0)*TGP2 + k] = __uint_as_float(f2tf32(x.x));
            shB[buf][(n4+1)*TGP2 + k] = __uint_as_float(f2tf32(x.y));
            shB[buf][(n4+2)*TGP2 + k] = __uint_as_float(f2tf32(x.z));
            shB[buf][(n4+3)*TGP2 + k] = __uint_as_float(f2tf32(x.w));
        }
    };

    stage(0, 0);
    __syncthreads();

    for (int c = 0; c < 14; c++) {             // 14 x 16 = 224 = NNP
        const int buf = c & 1;
        if (c + 1 < 14) stage(c + 1, buf ^ 1);
#pragma unroll
        for (int ks = 0; ks < 2; ks++) {
            const int kk = ks * 8;
            uint32_t ah[2][4];
#pragma unroll
            for (int ma = 0; ma < 2; ma++) {
                int r = warp_m + ma*16 + gid;
                const float* ph = &shA[buf][r*TGP2 + kk + tig];
                ah[ma][0] = __float_as_uint(ph[0]);
                ah[ma][1] = __float_as_uint(ph[8*TGP2]);
                ah[ma][2] = __float_as_uint(ph[4]);
                ah[ma][3] = __float_as_uint(ph[8*TGP2 + 4]);
            }
#pragma unroll
            for (int na = 0; na < 4; na++) {
                int cn = warp_n + na*8 + gid;
                uint32_t b0 = __float_as_uint(shB[buf][cn*TGP2 + kk + tig]);
                uint32_t b1 = __float_as_uint(shB[buf][cn*TGP2 + kk + tig + 4]);
#pragma unroll
                for (int ma = 0; ma < 2; ma++)
                    mma_tf32(acc[ma][na], ah[ma][0], ah[ma][1], ah[ma][2], ah[ma][3], b0, b1);
            }
        }
        __syncthreads();
    }

#pragma unroll
    for (int ma = 0; ma < 2; ma++) {
#pragma unroll
        for (int na = 0; na < 4; na++) {
            int colg = warp_n + na*8 + 2*tig;
#pragma unroll
            for (int half = 0; half < 2; half++) {
                int n = n0 + warp_m + ma*16 + gid + half*8;
                if (n >= Nn) continue;
                float* p = g_oh + ((size_t)(b*Nn + n))*Cc + h*Dd + colg;
                p[0] = acc[ma][na][half*2 + 0];
                p[1] = acc[ma][na][half*2 + 1];
            }
        }
    }
}

// =====================================================================
// K3: in-place row softmax, one warp per row of length 197
// =====================================================================
__global__ __launch_bounds__(128) void k_softmax_rows(float* __restrict__ data,
                                                      int nrows)
{
    int warp = (blockIdx.x * blockDim.x + threadIdx.x) >> 5;
    int lane = threadIdx.x & 31;
    if (warp >= nrows) return;
    float* row = data + (size_t)warp * Nn;
    float v[7];
    float mx = -INFINITY;
#pragma unroll
    for (int i=0;i<7;i++) {
        int m = lane + i*32;
        v[i] = (m < Nn) ? row[m] : -INFINITY;
        mx = fmaxf(mx, v[i]);
    }
    mx = warpMax(mx);
    float s = 0.f;
#pragma unroll
    for (int i=0;i<7;i++) {
        int m = lane + i*32;
        v[i] = (m < Nn) ? __expf(v[i]-mx) : 0.f;
        s += v[i];
    }
    s = warpSum(s);
    float inv = 1.f / s;
#pragma unroll
    for (int i=0;i<7;i++) {
        int m = lane + i*32;
        if (m < Nn) row[m] = v[i]*inv;
    }
}

// =====================================================================
// K4: head-mix conv as flat GEMM per batch: C[12 x 38809] = W[12x12] @ In
// warp-per-8-col tile, smem-free, A (wl/ww) hoisted hi/lo (3-term split).
// mode 0: In = scores (flat), Out = probs buffer (flat logits)
// mode 1: In = probs (flat),  Out = g_attnW (padded rows, m<197 only)
// =====================================================================
__global__ __launch_bounds__(256) void k_conv(const float* __restrict__ In,
                                              const float* __restrict__ W,
                                              float* __restrict__ Out_ext,
                                              int mode)
{
    const int b = blockIdx.y;
    const int wid = (threadIdx.x) >> 5, lane = threadIdx.x & 31;
    const int gid = lane >> 2, tig = lane & 3;
    const int t = blockIdx.x * 8 + wid;
    const int c0 = t * 8;
    if (c0 >= NN) return;

    uint32_t ah[2][4], al[2][4];
#pragma unroll
    for (int kc = 0; kc < 2; kc++) {
#pragma unroll
        for (int q = 0; q < 4; q++) {
            int r = (q & 1) ? gid + 8 : gid;
            int k = kc*8 + tig + ((q >> 1) ? 4 : 0);
            float f = (r < 12 && k < 12) ? W[r*12 + k] : 0.f;
            ah[kc][q] = f2tf32(f);
            al[kc][q] = f2tf32(f - __uint_as_float(ah[kc][q]));
        }
    }

    const float* inb = In + (size_t)b * Hh * NN;
    float acc[4] = {0.f, 0.f, 0.f, 0.f};

#pragma unroll
    for (int kc = 0; kc < 2; kc++) {
        int k0 = kc*8 + tig, k1 = kc*8 + tig + 4;
        int col = c0 + gid;
        float x0 = 0.f, x1 = 0.f;
        if (col < NN) {
            if (k0 < 12) x0 = inb[(size_t)k0*NN + col];
            if (k1 < 12) x1 = inb[(size_t)k1*NN + col];
        }
        uint32_t bh0 = f2tf32(x0), bh1 = f2tf32(x1);
        uint32_t bl0 = f2tf32(x0 - __uint_as_float(bh0));
        uint32_t bl1 = f2tf32(x1 - __uint_as_float(bh1));
        mma_tf32(acc, ah[kc][0], ah[kc][1], ah[kc][2], ah[kc][3], bh0, bh1);
        mma_tf32(acc, al[kc][0], al[kc][1], al[kc][2], al[kc][3], bh0, bh1);
        mma_tf32(acc, ah[kc][0], ah[kc][1], ah[kc][2], ah[kc][3], bl0, bl1);
    }

#pragma unroll
    for (int half = 0; half < 2; half++) {
        int r = gid + half*8;
        if (r >= 12) continue;
#pragma unroll
        for (int j = 0; j < 2; j++) {
            int c = c0 + 2*tig + j;
            if (c >= NN) continue;
            float val = acc[half*2 + j];
            if (mode == 0) {
                Out_ext[((size_t)(b*Hh + r))*NN + c] = val;
            } else {
                int n = c / Nn, m = c - n*Nn;
                g_attnW[(((size_t)(b*Hh + r))*Nn + n)*NNP + m] = val;
            }
        }
    }
}

// =====================================================================
extern "C" void kernel_launch(void* const* d_in, const int* in_sizes, int n_in,
                              void* d_out, int out_size)
{
    const float* x       = (const float*)d_in[0];
    const float* w_qkv   = (const float*)d_in[1];
    const float* w_proj  = (const float*)d_in[2];
    const float* b_proj  = (const float*)d_in[3];
    const float* w_convl = (const float*)d_in[4];
    const float* w_convw = (const float*)d_in[5];

    float* out0       = (float*)d_out;                       // attention_output [B,N,C]
    float* out_scores = out0 + (size_t)M1*Cc;                // [B,H,N,N]
    float* out_probs  = out_scores + (size_t)BH*NN;          // [B,H,N,N]
    float* out_vm     = out_probs  + (size_t)BH*NN;          // [B,H,N,N]

    const int conv_tiles  = (NN + 7) / 8;                    // 4852
    const int conv_blocks = (conv_tiles + 7) / 8;            // 607

    // 1) QKV projection (pipelined TF32 mma): [6304,768]@[768,2304]
    k_tgemm<<<dim3(18, 50), 256>>>(x, 768, w_qkv, 2304, 768, 0, nullptr, nullptr);

    // 2) attention scores = (q*scale) k^T  and raw scaled v v^T
    k_bgemm_tf32<<<dim3(2, 2, BH), 256>>>(0, out_scores, SCALE);
    k_bgemm_tf32<<<dim3(2, 2, BH), 256>>>(1, out_vm, SCALE);

    // 3) softmax(v v^T * scale) -> value_map (in place)
    {
        int nrows = BH * Nn;
        int blocks = (nrows + 3) / 4;
        k_softmax_rows<<<blocks, 128>>>(out_vm, nrows);
    }

    // 4a) conv_l as flat GEMM: logits -> out_probs
    k_conv<<<dim3(conv_blocks, Bb), 256>>>(out_scores, w_convl, out_probs, 0);

    // 4b) softmax logits in place -> probs
    {
        int nrows = BH * Nn;
        int blocks = (nrows + 3) / 4;
        k_softmax_rows<<<blocks, 128>>>(out_probs, nrows);
    }

    // 4c) conv_w as flat GEMM: probs -> g_attnW (padded)
    k_conv<<<dim3(conv_blocks, Bb), 256>>>(out_probs, w_convw, nullptr, 1);

    // 5) attnW @ v (pipelined TF32 mma) -> head-interleaved scratch
    k_av_tf32<<<dim3(1, 2, BH), 256>>>();

    // 6) projection + bias (pipelined TF32 mma, A = g_oh device-side)
    k_tgemm<<<dim3(6, 50), 256>>>(nullptr, 768, w_proj, 768, 768, 1, b_proj, out0);
}

// round 13
// speedup vs baseline: 1.2772x; 1.2772x over previous
#include <cuda_runtime.h>
#include <cuda_fp16.h>
#include <cstdint>
#include <math.h>

#define Bb 32
#define Nn 197
#define Cc 768
#define Hh 12
#define Dd 64
#define NN (Nn*Nn)      // 38809
#define BH (Bb*Hh)      // 384
#define M1 (Bb*Nn)      // 6304
#define NNP 224         // padded attnW row stride (7*32, 16B aligned)
#define SCALE 0.125f

// ---------------- scratch (no allocations allowed) ----------------
__device__ float g_q[BH*Nn*Dd];      // [B,H,N,D]
__device__ float g_k[BH*Nn*Dd];
__device__ float g_v[BH*Nn*Dd];
__device__ float g_attnW[(size_t)BH*Nn*NNP];   // conv_w-mixed probs, padded rows (pads stay 0)
__device__ float g_oh[(size_t)M1*Cc];          // out heads, [B,N,C] pre-proj

// ---------------- warp reductions ----------------
__device__ __forceinline__ float warpMax(float v){
#pragma unroll
    for (int o=16;o>0;o>>=1) v = fmaxf(v, __shfl_xor_sync(0xffffffffu, v, o));
    return v;
}
__device__ __forceinline__ float warpSum(float v){
#pragma unroll
    for (int o=16;o>0;o>>=1) v += __shfl_xor_sync(0xffffffffu, v, o);
    return v;
}

// ---------------- mma helpers ----------------
__device__ __forceinline__ uint32_t f2tf32(float x) {
    uint32_t u;
    asm("cvt.rna.tf32.f32 %0, %1;" : "=r"(u) : "f"(x));
    return u;
}
__device__ __forceinline__ void mma_tf32(float* d,
                                         uint32_t a0, uint32_t a1, uint32_t a2, uint32_t a3,
                                         uint32_t b0, uint32_t b1) {
    asm volatile(
        "mma.sync.aligned.m16n8k8.row.col.f32.tf32.tf32.f32 "
        "{%0,%1,%2,%3}, {%4,%5,%6,%7}, {%8,%9}, {%0,%1,%2,%3};"
        : "+f"(d[0]), "+f"(d[1]), "+f"(d[2]), "+f"(d[3])
        : "r"(a0), "r"(a1), "r"(a2), "r"(a3), "r"(b0), "r"(b1));
}
__device__ __forceinline__ void mma_f16(float* d,
                                        uint32_t a0, uint32_t a1, uint32_t a2, uint32_t a3,
                                        uint32_t b0, uint32_t b1) {
    asm volatile(
        "mma.sync.aligned.m16n8k16.row.col.f32.f16.f16.f32 "
        "{%0,%1,%2,%3}, {%4,%5,%6,%7}, {%8,%9}, {%0,%1,%2,%3};"
        : "+f"(d[0]), "+f"(d[1]), "+f"(d[2]), "+f"(d[3])
        : "r"(a0), "r"(a1), "r"(a2), "r"(a3), "r"(b0), "r"(b1));
}
__device__ __forceinline__ uint32_t h2u(__half2 h) { return *(uint32_t*)&h; }

#define HS 40                     // smem row stride in halfs (32 + pad 8)

// =====================================================================
// K1/K6: dense GEMM via fp16 mma: C[M,N] = A[M,K] @ B[K,N]
// block 128x128, K-chunk 32 (2 k16 steps), 8 warps (2m x 4n).
// mode 0: A=x, qkv scatter. mode 1: A=g_oh (device symbol), proj+bias.
// =====================================================================
__global__ __launch_bounds__(256) void k_tgemm(const float* __restrict__ A_ext, int lda,
                                               const float* __restrict__ B, int ldb,
                                               int Ktot, int mode,
                                               const float* __restrict__ bias,
                                               float* __restrict__ out)
{
    __shared__ __align__(16) __half shA[128*HS];
    __shared__ __align__(16) __half shB[128*HS];

    const float* A = (mode == 1) ? g_oh : A_ext;

    const int tid  = threadIdx.x;
    const int wid  = tid >> 5, lane = tid & 31;
    const int gid  = lane >> 2, tig = lane & 3;
    const int warp_m = (wid >> 2) * 64;
    const int warp_n = (wid & 3) * 32;
    const int row0 = blockIdx.y * 128;
    const int col0 = blockIdx.x * 128;

    float acc[4][4][4] = {};

    const int nchunks = Ktot >> 5;
    for (int c = 0; c < nchunks; c++) {
        const int k0 = c << 5;
        // ---- stage A: 128 rows x 32 k ----
#pragma unroll
        for (int it = 0; it < 4; it++) {
            int e = it * 256 + tid;
            int r = e >> 3, k4 = (e & 7) * 4;
            int gr = row0 + r;
            float4 x = make_float4(0.f,0.f,0.f,0.f);
            if (gr < M1) x = *(const float4*)&A[(size_t)gr * lda + k0 + k4];
            *(__half2*)&shA[r*HS + k4    ] = __floats2half2_rn(x.x, x.y);
            *(__half2*)&shA[r*HS + k4 + 2] = __floats2half2_rn(x.z, x.w);
        }
        // ---- stage B: shB[n][k] from B[k][n] ----
#pragma unroll
        for (int it = 0; it < 4; it++) {
            int e = it * 256 + tid;
            int k = e >> 5, n4 = (e & 31) * 4;
            float4 x = *(const float4*)&B[(size_t)(k0 + k) * ldb + col0 + n4];
            shB[(n4+0)*HS + k] = __float2half_rn(x.x);
            shB[(n4+1)*HS + k] = __float2half_rn(x.y);
            shB[(n4+2)*HS + k] = __float2half_rn(x.z);
            shB[(n4+3)*HS + k] = __float2half_rn(x.w);
        }
        __syncthreads();
        // ---- 2 k16 steps ----
#pragma unroll
        for (int ks = 0; ks < 2; ks++) {
            const int kk = ks * 16;
            uint32_t ah[4][4];
#pragma unroll
            for (int ma = 0; ma < 4; ma++) {
                int r = warp_m + ma*16 + gid;
                ah[ma][0] = *(const uint32_t*)&shA[ r     *HS + kk + 2*tig    ];
                ah[ma][1] = *(const uint32_t*)&shA[(r + 8)*HS + kk + 2*tig    ];
                ah[ma][2] = *(const uint32_t*)&shA[ r     *HS + kk + 2*tig + 8];
                ah[ma][3] = *(const uint32_t*)&shA[(r + 8)*HS + kk + 2*tig + 8];
            }
#pragma unroll
            for (int na = 0; na < 4; na++) {
                int cn = warp_n + na*8 + gid;
                uint32_t b0 = *(const uint32_t*)&shB[cn*HS + kk + 2*tig    ];
                uint32_t b1 = *(const uint32_t*)&shB[cn*HS + kk + 2*tig + 8];
#pragma unroll
                for (int ma = 0; ma < 4; ma++)
                    mma_f16(acc[ma][na], ah[ma][0], ah[ma][1], ah[ma][2], ah[ma][3], b0, b1);
            }
        }
        __syncthreads();
    }

#pragma unroll
    for (int ma = 0; ma < 4; ma++) {
#pragma unroll
        for (int na = 0; na < 4; na++) {
            int colg = col0 + warp_n + na*8 + 2*tig;
#pragma unroll
            for (int half = 0; half < 2; half++) {
                int row = row0 + warp_m + ma*16 + gid + half*8;
                if (row >= M1) continue;
                float v0 = acc[ma][na][half*2 + 0];
                float v1 = acc[ma][na][half*2 + 1];
                if (mode == 0) {
                    int t = colg / 768;
                    int rem = colg - t*768;
                    int h = rem >> 6, d0 = rem & 63;
                    float* dst = (t==0) ? g_q : (t==1) ? g_k : g_v;
                    int b = row / Nn, n = row - b*Nn;
                    float* p = dst + ((size_t)(b*Hh + h)*Nn + n)*Dd + d0;
                    p[0] = v0; p[1] = v1;
                } else {
                    float* p = out + (size_t)row*768 + colg;
                    p[0] = v0 + bias[colg];
                    p[1] = v1 + bias[colg + 1];
                }
            }
        }
    }
}

// =====================================================================
// K2: batched NT GEMM (fp16 mma): out[z,n,m] = alpha*sum_d A[n,d]*B[m,d]
// block 128x128, K=64 (2 chunks of 32), 8 warps (2m x 4n).
// =====================================================================
__global__ __launch_bounds__(256) void k_bgemm_f16(int mode,
                                                   float* __restrict__ out,
                                                   float alpha)
{
    __shared__ __align__(16) __half shA[128*HS];
    __shared__ __align__(16) __half shB[128*HS];

    const int z = blockIdx.z;
    const float* Az = (mode==0 ? g_q : g_v) + (size_t)z*Nn*Dd;
    const float* Bz = (mode==0 ? g_k : g_v) + (size_t)z*Nn*Dd;
    float* Oz = out + (size_t)z*NN;

    const int tid  = threadIdx.x;
    const int wid  = tid >> 5, lane = tid & 31;
    const int gid  = lane >> 2, tig = lane & 3;
    const int warp_m = (wid >> 2) * 64;
    const int warp_n = (wid & 3) * 32;
    const int n0 = blockIdx.y * 128;
    const int m0 = blockIdx.x * 128;

    float acc[4][4][4] = {};

#pragma unroll
    for (int c = 0; c < 2; c++) {
        const int k0 = c << 5;
#pragma unroll
        for (int it = 0; it < 4; it++) {
            int e = it * 256 + tid;
            int r = e >> 3, k4 = (e & 7) * 4;
            int ga = n0 + r, gb = m0 + r;
            float4 xa = make_float4(0.f,0.f,0.f,0.f);
            float4 xb = make_float4(0.f,0.f,0.f,0.f);
            if (ga < Nn) xa = *(const float4*)&Az[(size_t)ga*Dd + k0 + k4];
            if (gb < Nn) xb = *(const float4*)&Bz[(size_t)gb*Dd + k0 + k4];
            *(__half2*)&shA[r*HS + k4    ] = __floats2half2_rn(xa.x, xa.y);
            *(__half2*)&shA[r*HS + k4 + 2] = __floats2half2_rn(xa.z, xa.w);
            *(__half2*)&shB[r*HS + k4    ] = __floats2half2_rn(xb.x, xb.y);
            *(__half2*)&shB[r*HS + k4 + 2] = __floats2half2_rn(xb.z, xb.w);
        }
        __syncthreads();
#pragma unroll
        for (int ks = 0; ks < 2; ks++) {
            const int kk = ks * 16;
            uint32_t ah[4][4];
#pragma unroll
            for (int ma = 0; ma < 4; ma++) {
                int r = warp_m + ma*16 + gid;
                ah[ma][0] = *(const uint32_t*)&shA[ r     *HS + kk + 2*tig    ];
                ah[ma][1] = *(const uint32_t*)&shA[(r + 8)*HS + kk + 2*tig    ];
                ah[ma][2] = *(const uint32_t*)&shA[ r     *HS + kk + 2*tig + 8];
                ah[ma][3] = *(const uint32_t*)&shA[(r + 8)*HS + kk + 2*tig + 8];
            }
#pragma unroll
            for (int na = 0; na < 4; na++) {
                int cn = warp_n + na*8 + gid;
                uint32_t b0 = *(const uint32_t*)&shB[cn*HS + kk + 2*tig    ];
                uint32_t b1 = *(const uint32_t*)&shB[cn*HS + kk + 2*tig + 8];
#pragma unroll
                for (int ma = 0; ma < 4; ma++)
                    mma_f16(acc[ma][na], ah[ma][0], ah[ma][1], ah[ma][2], ah[ma][3], b0, b1);
            }
        }
        __syncthreads();
    }

#pragma unroll
    for (int ma = 0; ma < 4; ma++) {
#pragma unroll
        for (int na = 0; na < 4; na++) {
            int mg = m0 + warp_n + na*8 + 2*tig;
#pragma unroll
            for (int half = 0; half < 2; half++) {
                int n = n0 + warp_m + ma*16 + gid + half*8;
                if (n >= Nn) continue;
                if (mg < Nn)     Oz[(size_t)n*Nn + mg]     = alpha*acc[ma][na][half*2+0];
                if (mg + 1 < Nn) Oz[(size_t)n*Nn + mg + 1] = alpha*acc[ma][na][half*2+1];
            }
        }
    }
}

// =====================================================================
// K5: av (fp16 mma): out[n,d] = sum_m attnW[n,m] * v[m,d]
// attnW rows padded to NNP=224 (pads exact zero). 7 chunks of 32.
// block 128x64, 8 warps (4m x 2n).
// =====================================================================
__global__ __launch_bounds__(256) void k_av_f16()
{
    __shared__ __align__(16) __half shA[128*HS];   // [n][k]
    __shared__ __align__(16) __half shB[64*HS];    // [d][k]

    const int z = blockIdx.z;
    const int b = z / Hh, h = z - b*Hh;
    const float* Az = g_attnW + (size_t)z*Nn*NNP;
    const float* Vz = g_v + (size_t)z*Nn*Dd;

    const int tid  = threadIdx.x;
    const int wid  = tid >> 5, lane = tid & 31;
    const int gid  = lane >> 2, tig = lane & 3;
    const int warp_m = (wid >> 1) * 32;
    const int warp_n = (wid & 1) * 32;
    const int n0 = blockIdx.y * 128;

    float acc[2][4][4] = {};

#pragma unroll 1
    for (int c = 0; c < 7; c++) {
        const int k0 = c << 5;
#pragma unroll
        for (int it = 0; it < 4; it++) {
            int e = it * 256 + tid;
            int r = e >> 3, k4 = (e & 7) * 4;
            int gr = n0 + r;
            float4 x = make_float4(0.f,0.f,0.f,0.f);
            if (gr < Nn) x = *(const float4*)&Az[(size_t)gr*NNP + k0 + k4];
            *(__half2*)&shA[r*HS + k4    ] = __floats2half2_rn(x.x, x.y);
            *(__half2*)&shA[r*HS + k4 + 2] = __floats2half2_rn(x.z, x.w);
        }
#pragma unroll
        for (int it = 0; it < 2; it++) {
            int e = it * 256 + tid;
            int k = e >> 4, n4 = (e & 15) * 4;
            float4 x = make_float4(0.f,0.f,0.f,0.f);
            if (k0 + k < Nn) x = *(const float4*)&Vz[(size_t)(k0 + k)*Dd + n4];
            shB[(n4+0)*HS + k] = __float2half_rn(x.x);
            shB[(n4+1)*HS + k] = __float2half_rn(x.y);
            shB[(n4+2)*HS + k] = __float2half_rn(x.z);
            shB[(n4+3)*HS + k] = __float2half_rn(x.w);
        }
        __syncthreads();
#pragma unroll
        for (int ks = 0; ks < 2; ks++) {
            const int kk = ks * 16;
            uint32_t ah[2][4];
#pragma unroll
            for (int ma = 0; ma < 2; ma++) {
                int r = warp_m + ma*16 + gid;
                ah[ma][0] = *(const uint32_t*)&shA[ r     *HS + kk + 2*tig    ];
                ah[ma][1] = *(const uint32_t*)&shA[(r + 8)*HS + kk + 2*tig    ];
                ah[ma][2] = *(const uint32_t*)&shA[ r     *HS + kk + 2*tig + 8];
                ah[ma][3] = *(const uint32_t*)&shA[(r + 8)*HS + kk + 2*tig + 8];
            }
#pragma unroll
            for (int na = 0; na < 4; na++) {
                int cn = warp_n + na*8 + gid;
                uint32_t b0 = *(const uint32_t*)&shB[cn*HS + kk + 2*tig    ];
                uint32_t b1 = *(const uint32_t*)&shB[cn*HS + kk + 2*tig + 8];
#pragma unroll
                for (int ma = 0; ma < 2; ma++)
                    mma_f16(acc[ma][na], ah[ma][0], ah[ma][1], ah[ma][2], ah[ma][3], b0, b1);
            }
        }
        __syncthreads();
    }

#pragma unroll
    for (int ma = 0; ma < 2; ma++) {
#pragma unroll
        for (int na = 0; na < 4; na++) {
            int colg = warp_n + na*8 + 2*tig;
#pragma unroll
            for (int half = 0; half < 2; half++) {
                int n = n0 + warp_m + ma*16 + gid + half*8;
                if (n >= Nn) continue;
                float* p = g_oh + ((size_t)(b*Nn + n))*Cc + h*Dd + colg;
                p[0] = acc[ma][na][half*2 + 0];
                p[1] = acc[ma][na][half*2 + 1];
            }
        }
    }
}

// =====================================================================
// K3: in-place row softmax, one warp per row of length 197
// =====================================================================
__global__ __launch_bounds__(128) void k_softmax_rows(float* __restrict__ data,
                                                      int nrows)
{
    int warp = (blockIdx.x * blockDim.x + threadIdx.x) >> 5;
    int lane = threadIdx.x & 31;
    if (warp >= nrows) return;
    float* row = data + (size_t)warp * Nn;
    float v[7];
    float mx = -INFINITY;
#pragma unroll
    for (int i=0;i<7;i++) {
        int m = lane + i*32;
        v[i] = (m < Nn) ? row[m] : -INFINITY;
        mx = fmaxf(mx, v[i]);
    }
    mx = warpMax(mx);
    float s = 0.f;
#pragma unroll
    for (int i=0;i<7;i++) {
        int m = lane + i*32;
        v[i] = (m < Nn) ? __expf(v[i]-mx) : 0.f;
        s += v[i];
    }
    s = warpSum(s);
    float inv = 1.f / s;
#pragma unroll
    for (int i=0;i<7;i++) {
        int m = lane + i*32;
        if (m < Nn) row[m] = v[i]*inv;
    }
}

// =====================================================================
// K4: head-mix conv as flat GEMM per batch: C[12 x 38809] = W[12x12] @ In
// warp-per-8-col tile, smem-free, tf32 3-term split (precision-critical).
// mode 0: In = scores (flat), Out = probs buffer (flat logits)
// mode 1: In = probs (flat),  Out = g_attnW (padded rows, m<197 only)
// =====================================================================
__global__ __launch_bounds__(256) void k_conv(const float* __restrict__ In,
                                              const float* __restrict__ W,
                                              float* __restrict__ Out_ext,
                                              int mode)
{
    const int b = blockIdx.y;
    const int wid = (threadIdx.x) >> 5, lane = threadIdx.x & 31;
    const int gid = lane >> 2, tig = lane & 3;
    const int t = blockIdx.x * 8 + wid;
    const int c0 = t * 8;
    if (c0 >= NN) return;

    uint32_t ah[2][4], al[2][4];
#pragma unroll
    for (int kc = 0; kc < 2; kc++) {
#pragma unroll
        for (int q = 0; q < 4; q++) {
            int r = (q & 1) ? gid + 8 : gid;
            int k = kc*8 + tig + ((q >> 1) ? 4 : 0);
            float f = (r < 12 && k < 12) ? W[r*12 + k] : 0.f;
            ah[kc][q] = f2tf32(f);
            al[kc][q] = f2tf32(f - __uint_as_float(ah[kc][q]));
        }
    }

    const float* inb = In + (size_t)b * Hh * NN;
    float acc[4] = {0.f, 0.f, 0.f, 0.f};

#pragma unroll
    for (int kc = 0; kc < 2; kc++) {
        int k0 = kc*8 + tig, k1 = kc*8 + tig + 4;
        int col = c0 + gid;
        float x0 = 0.f, x1 = 0.f;
        if (col < NN) {
            if (k0 < 12) x0 = inb[(size_t)k0*NN + col];
            if (k1 < 12) x1 = inb[(size_t)k1*NN + col];
        }
        uint32_t bh0 = f2tf32(x0), bh1 = f2tf32(x1);
        uint32_t bl0 = f2tf32(x0 - __uint_as_float(bh0));
        uint32_t bl1 = f2tf32(x1 - __uint_as_float(bh1));
        mma_tf32(acc, ah[kc][0], ah[kc][1], ah[kc][2], ah[kc][3], bh0, bh1);
        mma_tf32(acc, al[kc][0], al[kc][1], al[kc][2], al[kc][3], bh0, bh1);
        mma_tf32(acc, ah[kc][0], ah[kc][1], ah[kc][2], ah[kc][3], bl0, bl1);
    }

#pragma unroll
    for (int half = 0; half < 2; half++) {
        int r = gid + half*8;
        if (r >= 12) continue;
#pragma unroll
        for (int j = 0; j < 2; j++) {
            int c = c0 + 2*tig + j;
            if (c >= NN) continue;
            float val = acc[half*2 + j];
            if (mode == 0) {
                Out_ext[((size_t)(b*Hh + r))*NN + c] = val;
            } else {
                int n = c / Nn, m = c - n*Nn;
                g_attnW[(((size_t)(b*Hh + r))*Nn + n)*NNP + m] = val;
            }
        }
    }
}

// =====================================================================
extern "C" void kernel_launch(void* const* d_in, const int* in_sizes, int n_in,
                              void* d_out, int out_size)
{
    const float* x       = (const float*)d_in[0];
    const float* w_qkv   = (const float*)d_in[1];
    const float* w_proj  = (const float*)d_in[2];
    const float* b_proj  = (const float*)d_in[3];
    const float* w_convl = (const float*)d_in[4];
    const float* w_convw = (const float*)d_in[5];

    float* out0       = (float*)d_out;                       // attention_output [B,N,C]
    float* out_scores = out0 + (size_t)M1*Cc;                // [B,H,N,N]
    float* out_probs  = out_scores + (size_t)BH*NN;          // [B,H,N,N]
    float* out_vm     = out_probs  + (size_t)BH*NN;          // [B,H,N,N]

    const int conv_tiles  = (NN + 7) / 8;                    // 4852
    const int conv_blocks = (conv_tiles + 7) / 8;            // 607

    // 1) QKV projection (fp16 mma): [6304,768]@[768,2304]
    k_tgemm<<<dim3(18, 50), 256>>>(x, 768, w_qkv, 2304, 768, 0, nullptr, nullptr);

    // 2) attention scores = (q*scale) k^T  and raw scaled v v^T
    k_bgemm_f16<<<dim3(2, 2, BH), 256>>>(0, out_scores, SCALE);
    k_bgemm_f16<<<dim3(2, 2, BH), 256>>>(1, out_vm, SCALE);

    // 3) softmax(v v^T * scale) -> value_map (in place)
    {
        int nrows = BH * Nn;
        int blocks = (nrows + 3) / 4;
        k_softmax_rows<<<blocks, 128>>>(out_vm, nrows);
    }

    // 4a) conv_l as flat GEMM (tf32 3-term): logits -> out_probs
    k_conv<<<dim3(conv_blocks, Bb), 256>>>(out_scores, w_convl, out_probs, 0);

    // 4b) softmax logits in place -> probs
    {
        int nrows = BH * Nn;
        int blocks = (nrows + 3) / 4;
        k_softmax_rows<<<blocks, 128>>>(out_probs, nrows);
    }

    // 4c) conv_w as flat GEMM (tf32 3-term): probs -> g_attnW (padded)
    k_conv<<<dim3(conv_blocks, Bb), 256>>>(out_probs, w_convw, nullptr, 1);

    // 5) attnW @ v (fp16 mma) -> head-interleaved scratch
    k_av_f16<<<dim3(1, 2, BH), 256>>>();

    // 6) projection + bias (fp16 mma, A = g_oh device-side)
    k_tgemm<<<dim3(6, 50), 256>>>(nullptr, 768, w_proj, 768, 768, 1, b_proj, out0);
}

// round 14
// speedup vs baseline: 2.0171x; 1.5794x over previous
#include <cuda_runtime.h>
#include <cuda_fp16.h>
#include <cstdint>
#include <math.h>

#define Bb 32
#define Nn 197
#define Cc 768
#define Hh 12
#define Dd 64
#define NN (Nn*Nn)      // 38809
#define BH (Bb*Hh)      // 384
#define M1 (Bb*Nn)      // 6304
#define NNP 224         // padded attnW row stride (7*32)
#define SCALE 0.125f

// ---------------- scratch (no allocations allowed) ----------------
__device__ __half h_x[(size_t)M1*Cc];          // x in half
__device__ __half h_wqkvT[(size_t)3*Cc*Cc];    // w_qkv^T  [2304][768]
__device__ __half h_wprojT[(size_t)Cc*Cc];     // w_proj^T [768][768]
__device__ __half g_q[(size_t)BH*Nn*Dd];       // [B,H,N,D]
__device__ __half g_k[(size_t)BH*Nn*Dd];
__device__ __half g_v[(size_t)BH*Nn*Dd];
__device__ __half g_attnW[(size_t)BH*Nn*NNP];  // padded rows (pads stay 0)
__device__ __half g_oh[(size_t)M1*Cc];         // out heads pre-proj

// ---------------- warp reductions ----------------
__device__ __forceinline__ float warpMax(float v){
#pragma unroll
    for (int o=16;o>0;o>>=1) v = fmaxf(v, __shfl_xor_sync(0xffffffffu, v, o));
    return v;
}
__device__ __forceinline__ float warpSum(float v){
#pragma unroll
    for (int o=16;o>0;o>>=1) v += __shfl_xor_sync(0xffffffffu, v, o);
    return v;
}

// ---------------- mma helpers ----------------
__device__ __forceinline__ uint32_t f2tf32(float x) {
    uint32_t u;
    asm("cvt.rna.tf32.f32 %0, %1;" : "=r"(u) : "f"(x));
    return u;
}
__device__ __forceinline__ void mma_tf32(float* d,
                                         uint32_t a0, uint32_t a1, uint32_t a2, uint32_t a3,
                                         uint32_t b0, uint32_t b1) {
    asm volatile(
        "mma.sync.aligned.m16n8k8.row.col.f32.tf32.tf32.f32 "
        "{%0,%1,%2,%3}, {%4,%5,%6,%7}, {%8,%9}, {%0,%1,%2,%3};"
        : "+f"(d[0]), "+f"(d[1]), "+f"(d[2]), "+f"(d[3])
        : "r"(a0), "r"(a1), "r"(a2), "r"(a3), "r"(b0), "r"(b1));
}
__device__ __forceinline__ void mma_f16(float* d,
                                        uint32_t a0, uint32_t a1, uint32_t a2, uint32_t a3,
                                        uint32_t b0, uint32_t b1) {
    asm volatile(
        "mma.sync.aligned.m16n8k16.row.col.f32.f16.f16.f32 "
        "{%0,%1,%2,%3}, {%4,%5,%6,%7}, {%8,%9}, {%0,%1,%2,%3};"
        : "+f"(d[0]), "+f"(d[1]), "+f"(d[2]), "+f"(d[3])
        : "r"(a0), "r"(a1), "r"(a2), "r"(a3), "r"(b0), "r"(b1));
}

#define HS 40                     // smem row stride in halfs (32 + pad 8)

// =====================================================================
// P0: pre-convert x -> h_x (same layout), float4 pairs -> uint4 halfs
// =====================================================================
__global__ __launch_bounds__(256) void k_cvt_x(const float* __restrict__ X)
{
    size_t i = (size_t)(blockIdx.x * blockDim.x + threadIdx.x) * 8;
    if (i >= (size_t)M1*Cc) return;
    float4 a = *(const float4*)&X[i];
    float4 b = *(const float4*)&X[i + 4];
    __half2 h[4];
    h[0] = __floats2half2_rn(a.x, a.y);
    h[1] = __floats2half2_rn(a.z, a.w);
    h[2] = __floats2half2_rn(b.x, b.y);
    h[3] = __floats2half2_rn(b.z, b.w);
    *(uint4*)&h_x[i] = *(uint4*)h;
}

// =====================================================================
// P1: pre-convert + transpose weights: W[K,N] float -> WT[N,K] half
// mode 0: w_qkv (N=2304) -> h_wqkvT ; mode 1: w_proj (N=768) -> h_wprojT
// thread handles 8 k at fixed n.
// =====================================================================
__global__ __launch_bounds__(256) void k_cvt_T(const float* __restrict__ W,
                                               int Nw, int mode)
{
    int idx = blockIdx.x * blockDim.x + threadIdx.x;
    int kg = idx % (Cc/8), n = idx / (Cc/8);
    if (n >= Nw) return;
    int k0 = kg * 8;
    __half2 h[4];
#pragma unroll
    for (int i = 0; i < 4; i++) {
        float f0 = W[(size_t)(k0 + 2*i    )*Nw + n];
        float f1 = W[(size_t)(k0 + 2*i + 1)*Nw + n];
        h[i] = __floats2half2_rn(f0, f1);
    }
    __half* out = (mode == 0) ? h_wqkvT : h_wprojT;
    *(uint4*)&out[(size_t)n*Cc + k0] = *(uint4*)h;
}

// =====================================================================
// K1/K6: dense GEMM via fp16 mma: C = A[M,768] @ BT[N,768]^T
// block 128x128, K-chunk 32 (2 k16 steps), 8 warps (2m x 4n).
// mode 0: A=h_x, BT=h_wqkvT, qkv scatter. mode 1: A=g_oh, BT=h_wprojT, +bias.
// =====================================================================
__global__ __launch_bounds__(256) void k_tgemm(int mode,
                                               const float* __restrict__ bias,
                                               float* __restrict__ out)
{
    __shared__ __align__(16) __half shA[128*HS];
    __shared__ __align__(16) __half shB[128*HS];

    const __half* A  = (mode == 1) ? g_oh : h_x;
    const __half* BT = (mode == 1) ? h_wprojT : h_wqkvT;

    const int tid  = threadIdx.x;
    const int wid  = tid >> 5, lane = tid & 31;
    const int gid  = lane >> 2, tig = lane & 3;
    const int warp_m = (wid >> 2) * 64;
    const int warp_n = (wid & 3) * 32;
    const int row0 = blockIdx.y * 128;
    const int col0 = blockIdx.x * 128;

    float acc[4][4][4] = {};

    for (int c = 0; c < 24; c++) {          // 768/32
        const int k0 = c << 5;
        // ---- stage A: 128 rows x 32 k = 512 uint4, 2/thread ----
#pragma unroll
        for (int it = 0; it < 2; it++) {
            int e = it * 256 + tid;
            int r = e >> 2, k8 = (e & 3) * 8;
            int gr = row0 + r;
            uint4 v = make_uint4(0u,0u,0u,0u);
            if (gr < M1) v = *(const uint4*)&A[(size_t)gr*Cc + k0 + k8];
            *(uint4*)&shA[r*HS + k8] = v;
        }
        // ---- stage B: 128 cols x 32 k, BT row-major -> direct ----
#pragma unroll
        for (int it = 0; it < 2; it++) {
            int e = it * 256 + tid;
            int r = e >> 2, k8 = (e & 3) * 8;
            uint4 v = *(const uint4*)&BT[(size_t)(col0 + r)*Cc + k0 + k8];
            *(uint4*)&shB[r*HS + k8] = v;
        }
        __syncthreads();
#pragma unroll
        for (int ks = 0; ks < 2; ks++) {
            const int kk = ks * 16;
            uint32_t ah[4][4];
#pragma unroll
            for (int ma = 0; ma < 4; ma++) {
                int r = warp_m + ma*16 + gid;
                ah[ma][0] = *(const uint32_t*)&shA[ r     *HS + kk + 2*tig    ];
                ah[ma][1] = *(const uint32_t*)&shA[(r + 8)*HS + kk + 2*tig    ];
                ah[ma][2] = *(const uint32_t*)&shA[ r     *HS + kk + 2*tig + 8];
                ah[ma][3] = *(const uint32_t*)&shA[(r + 8)*HS + kk + 2*tig + 8];
            }
#pragma unroll
            for (int na = 0; na < 4; na++) {
                int cn = warp_n + na*8 + gid;
                uint32_t b0 = *(const uint32_t*)&shB[cn*HS + kk + 2*tig    ];
                uint32_t b1 = *(const uint32_t*)&shB[cn*HS + kk + 2*tig + 8];
#pragma unroll
                for (int ma = 0; ma < 4; ma++)
                    mma_f16(acc[ma][na], ah[ma][0], ah[ma][1], ah[ma][2], ah[ma][3], b0, b1);
            }
        }
        __syncthreads();
    }

#pragma unroll
    for (int ma = 0; ma < 4; ma++) {
#pragma unroll
        for (int na = 0; na < 4; na++) {
            int colg = col0 + warp_n + na*8 + 2*tig;
#pragma unroll
            for (int half = 0; half < 2; half++) {
                int row = row0 + warp_m + ma*16 + gid + half*8;
                if (row >= M1) continue;
                float v0 = acc[ma][na][half*2 + 0];
                float v1 = acc[ma][na][half*2 + 1];
                if (mode == 0) {
                    int t = colg / 768;
                    int rem = colg - t*768;
                    int h = rem >> 6, d0 = rem & 63;
                    __half* dst = (t==0) ? g_q : (t==1) ? g_k : g_v;
                    int b = row / Nn, n = row - b*Nn;
                    *(__half2*)&dst[((size_t)(b*Hh + h)*Nn + n)*Dd + d0] =
                        __floats2half2_rn(v0, v1);
                } else {
                    float* p = out + (size_t)row*768 + colg;
                    p[0] = v0 + bias[colg];
                    p[1] = v1 + bias[colg + 1];
                }
            }
        }
    }
}

// =====================================================================
// K2: batched NT GEMM (fp16): out[z,n,m] = alpha*sum_d A[n,d]*B[m,d]
// block 128x128, K=64 (2 chunks of 32), 8 warps (2m x 4n).
// =====================================================================
__global__ __launch_bounds__(256) void k_bgemm_f16(int mode,
                                                   float* __restrict__ out,
                                                   float alpha)
{
    __shared__ __align__(16) __half shA[128*HS];
    __shared__ __align__(16) __half shB[128*HS];

    const int z = blockIdx.z;
    const __half* Az = (mode==0 ? g_q : g_v) + (size_t)z*Nn*Dd;
    const __half* Bz = (mode==0 ? g_k : g_v) + (size_t)z*Nn*Dd;
    float* Oz = out + (size_t)z*NN;

    const int tid  = threadIdx.x;
    const int wid  = tid >> 5, lane = tid & 31;
    const int gid  = lane >> 2, tig = lane & 3;
    const int warp_m = (wid >> 2) * 64;
    const int warp_n = (wid & 3) * 32;
    const int n0 = blockIdx.y * 128;
    const int m0 = blockIdx.x * 128;

    float acc[4][4][4] = {};

#pragma unroll
    for (int c = 0; c < 2; c++) {
        const int k0 = c << 5;
#pragma unroll
        for (int it = 0; it < 2; it++) {
            int e = it * 256 + tid;
            int r = e >> 2, k8 = (e & 3) * 8;
            int ga = n0 + r, gb = m0 + r;
            uint4 va = make_uint4(0u,0u,0u,0u);
            uint4 vb = make_uint4(0u,0u,0u,0u);
            if (ga < Nn) va = *(const uint4*)&Az[(size_t)ga*Dd + k0 + k8];
            if (gb < Nn) vb = *(const uint4*)&Bz[(size_t)gb*Dd + k0 + k8];
            *(uint4*)&shA[r*HS + k8] = va;
            *(uint4*)&shB[r*HS + k8] = vb;
        }
        __syncthreads();
#pragma unroll
        for (int ks = 0; ks < 2; ks++) {
            const int kk = ks * 16;
            uint32_t ah[4][4];
#pragma unroll
            for (int ma = 0; ma < 4; ma++) {
                int r = warp_m + ma*16 + gid;
                ah[ma][0] = *(const uint32_t*)&shA[ r     *HS + kk + 2*tig    ];
                ah[ma][1] = *(const uint32_t*)&shA[(r + 8)*HS + kk + 2*tig    ];
                ah[ma][2] = *(const uint32_t*)&shA[ r     *HS + kk + 2*tig + 8];
                ah[ma][3] = *(const uint32_t*)&shA[(r + 8)*HS + kk + 2*tig + 8];
            }
#pragma unroll
            for (int na = 0; na < 4; na++) {
                int cn = warp_n + na*8 + gid;
                uint32_t b0 = *(const uint32_t*)&shB[cn*HS + kk + 2*tig    ];
                uint32_t b1 = *(const uint32_t*)&shB[cn*HS + kk + 2*tig + 8];
#pragma unroll
                for (int ma = 0; ma < 4; ma++)
                    mma_f16(acc[ma][na], ah[ma][0], ah[ma][1], ah[ma][2], ah[ma][3], b0, b1);
            }
        }
        __syncthreads();
    }

#pragma unroll
    for (int ma = 0; ma < 4; ma++) {
#pragma unroll
        for (int na = 0; na < 4; na++) {
            int mg = m0 + warp_n + na*8 + 2*tig;
#pragma unroll
            for (int half = 0; half < 2; half++) {
                int n = n0 + warp_m + ma*16 + gid + half*8;
                if (n >= Nn) continue;
                if (mg < Nn)     Oz[(size_t)n*Nn + mg]     = alpha*acc[ma][na][half*2+0];
                if (mg + 1 < Nn) Oz[(size_t)n*Nn + mg + 1] = alpha*acc[ma][na][half*2+1];
            }
        }
    }
}

// =====================================================================
// K5: av (fp16): out[n,d] = sum_m attnW[n,m] * v[m,d]
// attnW half padded NNP=224 (pads exact zero). 7 chunks of 32.
// block 128x64, 8 warps (4m x 2n).
// =====================================================================
__global__ __launch_bounds__(256) void k_av_f16()
{
    __shared__ __align__(16) __half shA[128*HS];   // [n][k]
    __shared__ __align__(16) __half shB[64*HS];    // [d][k]

    const int z = blockIdx.z;
    const int b = z / Hh, h = z - b*Hh;
    const __half* Az = g_attnW + (size_t)z*Nn*NNP;
    const __half* Vz = g_v + (size_t)z*Nn*Dd;

    const int tid  = threadIdx.x;
    const int wid  = tid >> 5, lane = tid & 31;
    const int gid  = lane >> 2, tig = lane & 3;
    const int warp_m = (wid >> 1) * 32;
    const int warp_n = (wid & 1) * 32;
    const int n0 = blockIdx.y * 128;

    float acc[2][4][4] = {};

#pragma unroll 1
    for (int c = 0; c < 7; c++) {
        const int k0 = c << 5;
        // ---- stage A: attnW half rows, 512 uint4, 2/thread ----
#pragma unroll
        for (int it = 0; it < 2; it++) {
            int e = it * 256 + tid;
            int r = e >> 2, k8 = (e & 3) * 8;
            int gr = n0 + r;
            uint4 v = make_uint4(0u,0u,0u,0u);
            if (gr < Nn) v = *(const uint4*)&Az[(size_t)gr*NNP + k0 + k8];
            *(uint4*)&shA[r*HS + k8] = v;
        }
        // ---- stage B: shB[d][k] from Vz[k][d]; 256 uint4, 1/thread ----
        {
            int k = tid >> 3, d8 = (tid & 7) * 8;
            __half tmp[8];
            *(uint4*)tmp = (k0 + k < Nn)
                ? *(const uint4*)&Vz[(size_t)(k0 + k)*Dd + d8]
                : make_uint4(0u,0u,0u,0u);
#pragma unroll
            for (int i = 0; i < 8; i++) shB[(d8 + i)*HS + k] = tmp[i];
        }
        __syncthreads();
#pragma unroll
        for (int ks = 0; ks < 2; ks++) {
            const int kk = ks * 16;
            uint32_t ah[2][4];
#pragma unroll
            for (int ma = 0; ma < 2; ma++) {
                int r = warp_m + ma*16 + gid;
                ah[ma][0] = *(const uint32_t*)&shA[ r     *HS + kk + 2*tig    ];
                ah[ma][1] = *(const uint32_t*)&shA[(r + 8)*HS + kk + 2*tig    ];
                ah[ma][2] = *(const uint32_t*)&shA[ r     *HS + kk + 2*tig + 8];
                ah[ma][3] = *(const uint32_t*)&shA[(r + 8)*HS + kk + 2*tig + 8];
            }
#pragma unroll
            for (int na = 0; na < 4; na++) {
                int cn = warp_n + na*8 + gid;
                uint32_t b0 = *(const uint32_t*)&shB[cn*HS + kk + 2*tig    ];
                uint32_t b1 = *(const uint32_t*)&shB[cn*HS + kk + 2*tig + 8];
#pragma unroll
                for (int ma = 0; ma < 2; ma++)
                    mma_f16(acc[ma][na], ah[ma][0], ah[ma][1], ah[ma][2], ah[ma][3], b0, b1);
            }
        }
        __syncthreads();
    }

#pragma unroll
    for (int ma = 0; ma < 2; ma++) {
#pragma unroll
        for (int na = 0; na < 4; na++) {
            int colg = warp_n + na*8 + 2*tig;
#pragma unroll
            for (int half = 0; half < 2; half++) {
                int n = n0 + warp_m + ma*16 + gid + half*8;
                if (n >= Nn) continue;
                *(__half2*)&g_oh[((size_t)(b*Nn + n))*Cc + h*Dd + colg] =
                    __floats2half2_rn(acc[ma][na][half*2 + 0], acc[ma][na][half*2 + 1]);
            }
        }
    }
}

// =====================================================================
// K3: in-place row softmax, one warp per row of length 197
// =====================================================================
__global__ __launch_bounds__(128) void k_softmax_rows(float* __restrict__ data,
                                                      int nrows)
{
    int warp = (blockIdx.x * blockDim.x + threadIdx.x) >> 5;
    int lane = threadIdx.x & 31;
    if (warp >= nrows) return;
    float* row = data + (size_t)warp * Nn;
    float v[7];
    float mx = -INFINITY;
#pragma unroll
    for (int i=0;i<7;i++) {
        int m = lane + i*32;
        v[i] = (m < Nn) ? row[m] : -INFINITY;
        mx = fmaxf(mx, v[i]);
    }
    mx = warpMax(mx);
    float s = 0.f;
#pragma unroll
    for (int i=0;i<7;i++) {
        int m = lane + i*32;
        v[i] = (m < Nn) ? __expf(v[i]-mx) : 0.f;
        s += v[i];
    }
    s = warpSum(s);
    float inv = 1.f / s;
#pragma unroll
    for (int i=0;i<7;i++) {
        int m = lane + i*32;
        if (m < Nn) row[m] = v[i]*inv;
    }
}

// =====================================================================
// K4: head-mix conv as flat GEMM per batch: C[12 x 38809] = W[12x12] @ In
// warp-per-8-col tile, smem-free, tf32 3-term split (precision-critical).
// mode 0: In = scores (flat), Out = probs buffer (flat logits, float)
// mode 1: In = probs (flat),  Out = g_attnW (half, padded rows)
// =====================================================================
__global__ __launch_bounds__(256) void k_conv(const float* __restrict__ In,
                                              const float* __restrict__ W,
                                              float* __restrict__ Out_ext,
                                              int mode)
{
    const int b = blockIdx.y;
    const int wid = (threadIdx.x) >> 5, lane = threadIdx.x & 31;
    const int gid = lane >> 2, tig = lane & 3;
    const int t = blockIdx.x * 8 + wid;
    const int c0 = t * 8;
    if (c0 >= NN) return;

    uint32_t ah[2][4], al[2][4];
#pragma unroll
    for (int kc = 0; kc < 2; kc++) {
#pragma unroll
        for (int q = 0; q < 4; q++) {
            int r = (q & 1) ? gid + 8 : gid;
            int k = kc*8 + tig + ((q >> 1) ? 4 : 0);
            float f = (r < 12 && k < 12) ? W[r*12 + k] : 0.f;
            ah[kc][q] = f2tf32(f);
            al[kc][q] = f2tf32(f - __uint_as_float(ah[kc][q]));
        }
    }

    const float* inb = In + (size_t)b * Hh * NN;
    float acc[4] = {0.f, 0.f, 0.f, 0.f};

#pragma unroll
    for (int kc = 0; kc < 2; kc++) {
        int k0 = kc*8 + tig, k1 = kc*8 + tig + 4;
        int col = c0 + gid;
        float x0 = 0.f, x1 = 0.f;
        if (col < NN) {
            if (k0 < 12) x0 = inb[(size_t)k0*NN + col];
            if (k1 < 12) x1 = inb[(size_t)k1*NN + col];
        }
        uint32_t bh0 = f2tf32(x0), bh1 = f2tf32(x1);
        uint32_t bl0 = f2tf32(x0 - __uint_as_float(bh0));
        uint32_t bl1 = f2tf32(x1 - __uint_as_float(bh1));
        mma_tf32(acc, ah[kc][0], ah[kc][1], ah[kc][2], ah[kc][3], bh0, bh1);
        mma_tf32(acc, al[kc][0], al[kc][1], al[kc][2], al[kc][3], bh0, bh1);
        mma_tf32(acc, ah[kc][0], ah[kc][1], ah[kc][2], ah[kc][3], bl0, bl1);
    }

#pragma unroll
    for (int half = 0; half < 2; half++) {
        int r = gid + half*8;
        if (r >= 12) continue;
#pragma unroll
        for (int j = 0; j < 2; j++) {
            int c = c0 + 2*tig + j;
            if (c >= NN) continue;
            float val = acc[half*2 + j];
            if (mode == 0) {
                Out_ext[((size_t)(b*Hh + r))*NN + c] = val;
            } else {
                int n = c / Nn, m = c - n*Nn;
                g_attnW[(((size_t)(b*Hh + r))*Nn + n)*NNP + m] = __float2half_rn(val);
            }
        }
    }
}

// =====================================================================
extern "C" void kernel_launch(void* const* d_in, const int* in_sizes, int n_in,
                              void* d_out, int out_size)
{
    const float* x       = (const float*)d_in[0];
    const float* w_qkv   = (const float*)d_in[1];
    const float* w_proj  = (const float*)d_in[2];
    const float* b_proj  = (const float*)d_in[3];
    const float* w_convl = (const float*)d_in[4];
    const float* w_convw = (const float*)d_in[5];

    float* out0       = (float*)d_out;                       // attention_output [B,N,C]
    float* out_scores = out0 + (size_t)M1*Cc;                // [B,H,N,N]
    float* out_probs  = out_scores + (size_t)BH*NN;          // [B,H,N,N]
    float* out_vm     = out_probs  + (size_t)BH*NN;          // [B,H,N,N]

    const int conv_tiles  = (NN + 7) / 8;                    // 4852
    const int conv_blocks = (conv_tiles + 7) / 8;            // 607

    // 0) pre-convert inputs to half (x same-layout; weights transposed)
    {
        int nx = (M1*Cc/8 + 255) / 256;
        k_cvt_x<<<nx, 256>>>(x);
        int nq = (3*Cc*(Cc/8) + 255) / 256;
        k_cvt_T<<<nq, 256>>>(w_qkv, 3*Cc, 0);
        int np = (Cc*(Cc/8) + 255) / 256;
        k_cvt_T<<<np, 256>>>(w_proj, Cc, 1);
    }

    // 1) QKV projection (fp16 mma): [6304,768]@[768,2304]
    k_tgemm<<<dim3(18, 50), 256>>>(0, nullptr, nullptr);

    // 2) attention scores = (q*scale) k^T  and raw scaled v v^T
    k_bgemm_f16<<<dim3(2, 2, BH), 256>>>(0, out_scores, SCALE);
    k_bgemm_f16<<<dim3(2, 2, BH), 256>>>(1, out_vm, SCALE);

    // 3) softmax(v v^T * scale) -> value_map (in place)
    {
        int nrows = BH * Nn;
        int blocks = (nrows + 3) / 4;
        k_softmax_rows<<<blocks, 128>>>(out_vm, nrows);
    }

    // 4a) conv_l as flat GEMM (tf32 3-term): logits -> out_probs
    k_conv<<<dim3(conv_blocks, Bb), 256>>>(out_scores, w_convl, out_probs, 0);

    // 4b) softmax logits in place -> probs
    {
        int nrows = BH * Nn;
        int blocks = (nrows + 3) / 4;
        k_softmax_rows<<<blocks, 128>>>(out_probs, nrows);
    }

    // 4c) conv_w as flat GEMM (tf32 3-term): probs -> g_attnW (half, padded)
    k_conv<<<dim3(conv_blocks, Bb), 256>>>(out_probs, w_convw, nullptr, 1);

    // 5) attnW @ v (fp16 mma) -> head-interleaved half scratch
    k_av_f16<<<dim3(1, 2, BH), 256>>>();

    // 6) projection + bias (fp16 mma, operands device-side)
    k_tgemm<<<dim3(6, 50), 256>>>(1, b_proj, out0);
}

// round 15
// speedup vs baseline: 2.0173x; 1.0001x over previous
#include <cuda_runtime.h>
#include <cuda_fp16.h>
#include <cstdint>
#include <math.h>

#define Bb 32
#define Nn 197
#define Cc 768
#define Hh 12
#define Dd 64
#define NN (Nn*Nn)      // 38809
#define BH (Bb*Hh)      // 384
#define M1 (Bb*Nn)      // 6304
#define NNP 224         // padded attnW row stride (7*32)
#define SCALE 0.125f

// ---------------- scratch (no allocations allowed) ----------------
__device__ __half h_x[(size_t)M1*Cc];          // x in half
__device__ __half h_wqkvT[(size_t)3*Cc*Cc];    // w_qkv^T  [2304][768]
__device__ __half h_wprojT[(size_t)Cc*Cc];     // w_proj^T [768][768]
__device__ __half g_q[(size_t)BH*Nn*Dd];       // [B,H,N,D]
__device__ __half g_k[(size_t)BH*Nn*Dd];
__device__ __half g_v[(size_t)BH*Nn*Dd];
__device__ __half g_attnW[(size_t)BH*Nn*NNP];  // padded rows (pads stay 0)
__device__ __half g_oh[(size_t)M1*Cc];         // out heads pre-proj

// ---------------- warp reductions ----------------
__device__ __forceinline__ float warpMax(float v){
#pragma unroll
    for (int o=16;o>0;o>>=1) v = fmaxf(v, __shfl_xor_sync(0xffffffffu, v, o));
    return v;
}
__device__ __forceinline__ float warpSum(float v){
#pragma unroll
    for (int o=16;o>0;o>>=1) v += __shfl_xor_sync(0xffffffffu, v, o);
    return v;
}

// ---------------- mma helpers ----------------
__device__ __forceinline__ uint32_t f2tf32(float x) {
    uint32_t u;
    asm("cvt.rna.tf32.f32 %0, %1;" : "=r"(u) : "f"(x));
    return u;
}
__device__ __forceinline__ void mma_tf32(float* d,
                                         uint32_t a0, uint32_t a1, uint32_t a2, uint32_t a3,
                                         uint32_t b0, uint32_t b1) {
    asm volatile(
        "mma.sync.aligned.m16n8k8.row.col.f32.tf32.tf32.f32 "
        "{%0,%1,%2,%3}, {%4,%5,%6,%7}, {%8,%9}, {%0,%1,%2,%3};"
        : "+f"(d[0]), "+f"(d[1]), "+f"(d[2]), "+f"(d[3])
        : "r"(a0), "r"(a1), "r"(a2), "r"(a3), "r"(b0), "r"(b1));
}
__device__ __forceinline__ void mma_f16(float* d,
                                        uint32_t a0, uint32_t a1, uint32_t a2, uint32_t a3,
                                        uint32_t b0, uint32_t b1) {
    asm volatile(
        "mma.sync.aligned.m16n8k16.row.col.f32.f16.f16.f32 "
        "{%0,%1,%2,%3}, {%4,%5,%6,%7}, {%8,%9}, {%0,%1,%2,%3};"
        : "+f"(d[0]), "+f"(d[1]), "+f"(d[2]), "+f"(d[3])
        : "r"(a0), "r"(a1), "r"(a2), "r"(a3), "r"(b0), "r"(b1));
}
__device__ __forceinline__ void ldsm_x4(uint32_t& r0, uint32_t& r1,
                                        uint32_t& r2, uint32_t& r3, uint32_t addr) {
    asm volatile("ldmatrix.sync.aligned.m8n8.x4.shared.b16 {%0,%1,%2,%3}, [%4];"
                 : "=r"(r0), "=r"(r1), "=r"(r2), "=r"(r3) : "r"(addr));
}

#define HS 40                     // smem row stride in halfs (32 + pad 8)

// =====================================================================
// P0: pre-convert x -> h_x
// =====================================================================
__global__ __launch_bounds__(256) void k_cvt_x(const float* __restrict__ X)
{
    size_t i = (size_t)(blockIdx.x * blockDim.x + threadIdx.x) * 8;
    if (i >= (size_t)M1*Cc) return;
    float4 a = *(const float4*)&X[i];
    float4 b = *(const float4*)&X[i + 4];
    __half2 h[4];
    h[0] = __floats2half2_rn(a.x, a.y);
    h[1] = __floats2half2_rn(a.z, a.w);
    h[2] = __floats2half2_rn(b.x, b.y);
    h[3] = __floats2half2_rn(b.z, b.w);
    *(uint4*)&h_x[i] = *(uint4*)h;
}

// =====================================================================
// P1: pre-convert + transpose weights: W[K,N] float -> WT[N,K] half
// =====================================================================
__global__ __launch_bounds__(256) void k_cvt_T(const float* __restrict__ W,
                                               int Nw, int mode)
{
    int idx = blockIdx.x * blockDim.x + threadIdx.x;
    int kg = idx % (Cc/8), n = idx / (Cc/8);
    if (n >= Nw) return;
    int k0 = kg * 8;
    __half2 h[4];
#pragma unroll
    for (int i = 0; i < 4; i++) {
        float f0 = W[(size_t)(k0 + 2*i    )*Nw + n];
        float f1 = W[(size_t)(k0 + 2*i + 1)*Nw + n];
        h[i] = __floats2half2_rn(f0, f1);
    }
    __half* out = (mode == 0) ? h_wqkvT : h_wprojT;
    *(uint4*)&out[(size_t)n*Cc + k0] = *(uint4*)h;
}

// =====================================================================
// K1/K6: dense GEMM via fp16 mma + ldmatrix: C = A[M,768] @ BT[N,768]^T
// block 128x128, K-chunk 32 (2 k16 steps), 8 warps (2m x 4n).
// =====================================================================
__global__ __launch_bounds__(256) void k_tgemm(int mode,
                                               const float* __restrict__ bias,
                                               float* __restrict__ out)
{
    __shared__ __align__(16) __half shA[128*HS];
    __shared__ __align__(16) __half shB[128*HS];

    const __half* A  = (mode == 1) ? g_oh : h_x;
    const __half* BT = (mode == 1) ? h_wprojT : h_wqkvT;

    const int tid  = threadIdx.x;
    const int wid  = tid >> 5, lane = tid & 31;
    const int gid  = lane >> 2, tig = lane & 3;
    const int warp_m = (wid >> 2) * 64;
    const int warp_n = (wid & 3) * 32;
    const int row0 = blockIdx.y * 128;
    const int col0 = blockIdx.x * 128;

    const uint32_t aBase = (uint32_t)__cvta_generic_to_shared(shA);
    const uint32_t bBase = (uint32_t)__cvta_generic_to_shared(shB);
    // ldmatrix lane-address components
    const int aRow = warp_m + (lane & 15);        // + ma*16
    const int aKh  = ((lane >> 4) & 1) * 8;       // k half
    const int bG   = lane >> 3;                   // 0..3
    const int bCol = warp_n + ((bG >> 1) * 8) + (lane & 7);  // + p*16
    const int bKh  = (bG & 1) * 8;

    float acc[4][4][4] = {};

    for (int c = 0; c < 24; c++) {          // 768/32
        const int k0 = c << 5;
#pragma unroll
        for (int it = 0; it < 2; it++) {
            int e = it * 256 + tid;
            int r = e >> 2, k8 = (e & 3) * 8;
            int gr = row0 + r;
            uint4 v = make_uint4(0u,0u,0u,0u);
            if (gr < M1) v = *(const uint4*)&A[(size_t)gr*Cc + k0 + k8];
            *(uint4*)&shA[r*HS + k8] = v;
        }
#pragma unroll
        for (int it = 0; it < 2; it++) {
            int e = it * 256 + tid;
            int r = e >> 2, k8 = (e & 3) * 8;
            uint4 v = *(const uint4*)&BT[(size_t)(col0 + r)*Cc + k0 + k8];
            *(uint4*)&shB[r*HS + k8] = v;
        }
        __syncthreads();
#pragma unroll
        for (int ks = 0; ks < 2; ks++) {
            const int kk = ks * 16;
            uint32_t ah[4][4];
#pragma unroll
            for (int ma = 0; ma < 4; ma++) {
                uint32_t addr = aBase + (uint32_t)(((aRow + ma*16)*HS + kk + aKh) * 2);
                ldsm_x4(ah[ma][0], ah[ma][1], ah[ma][2], ah[ma][3], addr);
            }
            uint32_t bf[4][2];
#pragma unroll
            for (int p = 0; p < 2; p++) {
                uint32_t addr = bBase + (uint32_t)(((bCol + p*16)*HS + kk + bKh) * 2);
                uint32_t r0, r1, r2, r3;
                ldsm_x4(r0, r1, r2, r3, addr);
                bf[p*2  ][0] = r0; bf[p*2  ][1] = r1;
                bf[p*2+1][0] = r2; bf[p*2+1][1] = r3;
            }
#pragma unroll
            for (int na = 0; na < 4; na++)
#pragma unroll
                for (int ma = 0; ma < 4; ma++)
                    mma_f16(acc[ma][na], ah[ma][0], ah[ma][1], ah[ma][2], ah[ma][3],
                            bf[na][0], bf[na][1]);
        }
        __syncthreads();
    }

#pragma unroll
    for (int ma = 0; ma < 4; ma++) {
#pragma unroll
        for (int na = 0; na < 4; na++) {
            int colg = col0 + warp_n + na*8 + 2*tig;
#pragma unroll
            for (int half = 0; half < 2; half++) {
                int row = row0 + warp_m + ma*16 + gid + half*8;
                if (row >= M1) continue;
                float v0 = acc[ma][na][half*2 + 0];
                float v1 = acc[ma][na][half*2 + 1];
                if (mode == 0) {
                    int t = colg / 768;
                    int rem = colg - t*768;
                    int h = rem >> 6, d0 = rem & 63;
                    __half* dst = (t==0) ? g_q : (t==1) ? g_k : g_v;
                    int b = row / Nn, n = row - b*Nn;
                    *(__half2*)&dst[((size_t)(b*Hh + h)*Nn + n)*Dd + d0] =
                        __floats2half2_rn(v0, v1);
                } else {
                    float* p = out + (size_t)row*768 + colg;
                    p[0] = v0 + bias[colg];
                    p[1] = v1 + bias[colg + 1];
                }
            }
        }
    }
}

// =====================================================================
// K2: batched NT GEMM (fp16 + ldmatrix): out[z,n,m] = alpha*sum A*B
// block 128x128, K=64 (2 chunks of 32), 8 warps (2m x 4n).
// =====================================================================
__global__ __launch_bounds__(256) void k_bgemm_f16(int mode,
                                                   float* __restrict__ out,
                                                   float alpha)
{
    __shared__ __align__(16) __half shA[128*HS];
    __shared__ __align__(16) __half shB[128*HS];

    const int z = blockIdx.z;
    const __half* Az = (mode==0 ? g_q : g_v) + (size_t)z*Nn*Dd;
    const __half* Bz = (mode==0 ? g_k : g_v) + (size_t)z*Nn*Dd;
    float* Oz = out + (size_t)z*NN;

    const int tid  = threadIdx.x;
    const int wid  = tid >> 5, lane = tid & 31;
    const int gid  = lane >> 2, tig = lane & 3;
    const int warp_m = (wid >> 2) * 64;
    const int warp_n = (wid & 3) * 32;
    const int n0 = blockIdx.y * 128;
    const int m0 = blockIdx.x * 128;

    const uint32_t aBase = (uint32_t)__cvta_generic_to_shared(shA);
    const uint32_t bBase = (uint32_t)__cvta_generic_to_shared(shB);
    const int aRow = warp_m + (lane & 15);
    const int aKh  = ((lane >> 4) & 1) * 8;
    const int bG   = lane >> 3;
    const int bCol = warp_n + ((bG >> 1) * 8) + (lane & 7);
    const int bKh  = (bG & 1) * 8;

    float acc[4][4][4] = {};

#pragma unroll
    for (int c = 0; c < 2; c++) {
        const int k0 = c << 5;
#pragma unroll
        for (int it = 0; it < 2; it++) {
            int e = it * 256 + tid;
            int r = e >> 2, k8 = (e & 3) * 8;
            int ga = n0 + r, gb = m0 + r;
            uint4 va = make_uint4(0u,0u,0u,0u);
            uint4 vb = make_uint4(0u,0u,0u,0u);
            if (ga < Nn) va = *(const uint4*)&Az[(size_t)ga*Dd + k0 + k8];
            if (gb < Nn) vb = *(const uint4*)&Bz[(size_t)gb*Dd + k0 + k8];
            *(uint4*)&shA[r*HS + k8] = va;
            *(uint4*)&shB[r*HS + k8] = vb;
        }
        __syncthreads();
#pragma unroll
        for (int ks = 0; ks < 2; ks++) {
            const int kk = ks * 16;
            uint32_t ah[4][4];
#pragma unroll
            for (int ma = 0; ma < 4; ma++) {
                uint32_t addr = aBase + (uint32_t)(((aRow + ma*16)*HS + kk + aKh) * 2);
                ldsm_x4(ah[ma][0], ah[ma][1], ah[ma][2], ah[ma][3], addr);
            }
            uint32_t bf[4][2];
#pragma unroll
            for (int p = 0; p < 2; p++) {
                uint32_t addr = bBase + (uint32_t)(((bCol + p*16)*HS + kk + bKh) * 2);
                uint32_t r0, r1, r2, r3;
                ldsm_x4(r0, r1, r2, r3, addr);
                bf[p*2  ][0] = r0; bf[p*2  ][1] = r1;
                bf[p*2+1][0] = r2; bf[p*2+1][1] = r3;
            }
#pragma unroll
            for (int na = 0; na < 4; na++)
#pragma unroll
                for (int ma = 0; ma < 4; ma++)
                    mma_f16(acc[ma][na], ah[ma][0], ah[ma][1], ah[ma][2], ah[ma][3],
                            bf[na][0], bf[na][1]);
        }
        __syncthreads();
    }

#pragma unroll
    for (int ma = 0; ma < 4; ma++) {
#pragma unroll
        for (int na = 0; na < 4; na++) {
            int mg = m0 + warp_n + na*8 + 2*tig;
#pragma unroll
            for (int half = 0; half < 2; half++) {
                int n = n0 + warp_m + ma*16 + gid + half*8;
                if (n >= Nn) continue;
                if (mg < Nn)     Oz[(size_t)n*Nn + mg]     = alpha*acc[ma][na][half*2+0];
                if (mg + 1 < Nn) Oz[(size_t)n*Nn + mg + 1] = alpha*acc[ma][na][half*2+1];
            }
        }
    }
}

// =====================================================================
// K5: av (fp16 + ldmatrix): out[n,d] = sum_m attnW[n,m] * v[m,d]
// block 128x64, 7 chunks of 32, 8 warps (4m x 2n).
// =====================================================================
__global__ __launch_bounds__(256) void k_av_f16()
{
    __shared__ __align__(16) __half shA[128*HS];   // [n][k]
    __shared__ __align__(16) __half shB[64*HS];    // [d][k]

    const int z = blockIdx.z;
    const int b = z / Hh, h = z - b*Hh;
    const __half* Az = g_attnW + (size_t)z*Nn*NNP;
    const __half* Vz = g_v + (size_t)z*Nn*Dd;

    const int tid  = threadIdx.x;
    const int wid  = tid >> 5, lane = tid & 31;
    const int gid  = lane >> 2, tig = lane & 3;
    const int warp_m = (wid >> 1) * 32;
    const int warp_n = (wid & 1) * 32;
    const int n0 = blockIdx.y * 128;

    const uint32_t aBase = (uint32_t)__cvta_generic_to_shared(shA);
    const uint32_t bBase = (uint32_t)__cvta_generic_to_shared(shB);
    const int aRow = warp_m + (lane & 15);
    const int aKh  = ((lane >> 4) & 1) * 8;
    const int bG   = lane >> 3;
    const int bCol = warp_n + ((bG >> 1) * 8) + (lane & 7);
    const int bKh  = (bG & 1) * 8;

    float acc[2][4][4] = {};

#pragma unroll 1
    for (int c = 0; c < 7; c++) {
        const int k0 = c << 5;
#pragma unroll
        for (int it = 0; it < 2; it++) {
            int e = it * 256 + tid;
            int r = e >> 2, k8 = (e & 3) * 8;
            int gr = n0 + r;
            uint4 v = make_uint4(0u,0u,0u,0u);
            if (gr < Nn) v = *(const uint4*)&Az[(size_t)gr*NNP + k0 + k8];
            *(uint4*)&shA[r*HS + k8] = v;
        }
        {
            int k = tid >> 3, d8 = (tid & 7) * 8;
            __half tmp[8];
            *(uint4*)tmp = (k0 + k < Nn)
                ? *(const uint4*)&Vz[(size_t)(k0 + k)*Dd + d8]
                : make_uint4(0u,0u,0u,0u);
#pragma unroll
            for (int i = 0; i < 8; i++) shB[(d8 + i)*HS + k] = tmp[i];
        }
        __syncthreads();
#pragma unroll
        for (int ks = 0; ks < 2; ks++) {
            const int kk = ks * 16;
            uint32_t ah[2][4];
#pragma unroll
            for (int ma = 0; ma < 2; ma++) {
                uint32_t addr = aBase + (uint32_t)(((aRow + ma*16)*HS + kk + aKh) * 2);
                ldsm_x4(ah[ma][0], ah[ma][1], ah[ma][2], ah[ma][3], addr);
            }
            uint32_t bf[4][2];
#pragma unroll
            for (int p = 0; p < 2; p++) {
                uint32_t addr = bBase + (uint32_t)(((bCol + p*16)*HS + kk + bKh) * 2);
                uint32_t r0, r1, r2, r3;
                ldsm_x4(r0, r1, r2, r3, addr);
                bf[p*2  ][0] = r0; bf[p*2  ][1] = r1;
                bf[p*2+1][0] = r2; bf[p*2+1][1] = r3;
            }
#pragma unroll
            for (int na = 0; na < 4; na++)
#pragma unroll
                for (int ma = 0; ma < 2; ma++)
                    mma_f16(acc[ma][na], ah[ma][0], ah[ma][1], ah[ma][2], ah[ma][3],
                            bf[na][0], bf[na][1]);
        }
        __syncthreads();
    }

#pragma unroll
    for (int ma = 0; ma < 2; ma++) {
#pragma unroll
        for (int na = 0; na < 4; na++) {
            int colg = warp_n + na*8 + 2*tig;
#pragma unroll
            for (int half = 0; half < 2; half++) {
                int n = n0 + warp_m + ma*16 + gid + half*8;
                if (n >= Nn) continue;
                *(__half2*)&g_oh[((size_t)(b*Nn + n))*Cc + h*Dd + colg] =
                    __floats2half2_rn(acc[ma][na][half*2 + 0], acc[ma][na][half*2 + 1]);
            }
        }
    }
}

// =====================================================================
// K3: in-place row softmax, one warp per row of length 197
// =====================================================================
__global__ __launch_bounds__(128) void k_softmax_rows(float* __restrict__ data,
                                                      int nrows)
{
    int warp = (blockIdx.x * blockDim.x + threadIdx.x) >> 5;
    int lane = threadIdx.x & 31;
    if (warp >= nrows) return;
    float* row = data + (size_t)warp * Nn;
    float v[7];
    float mx = -INFINITY;
#pragma unroll
    for (int i=0;i<7;i++) {
        int m = lane + i*32;
        v[i] = (m < Nn) ? row[m] : -INFINITY;
        mx = fmaxf(mx, v[i]);
    }
    mx = warpMax(mx);
    float s = 0.f;
#pragma unroll
    for (int i=0;i<7;i++) {
        int m = lane + i*32;
        v[i] = (m < Nn) ? __expf(v[i]-mx) : 0.f;
        s += v[i];
    }
    s = warpSum(s);
    float inv = 1.f / s;
#pragma unroll
    for (int i=0;i<7;i++) {
        int m = lane + i*32;
        if (m < Nn) row[m] = v[i]*inv;
    }
}

// =====================================================================
// K4: head-mix conv as flat GEMM per batch (tf32 3-term split)
// mode 0: scores -> probs logits (float). mode 1: probs -> g_attnW (half).
// =====================================================================
__global__ __launch_bounds__(256) void k_conv(const float* __restrict__ In,
                                              const float* __restrict__ W,
                                              float* __restrict__ Out_ext,
                                              int mode)
{
    const int b = blockIdx.y;
    const int wid = (threadIdx.x) >> 5, lane = threadIdx.x & 31;
    const int gid = lane >> 2, tig = lane & 3;
    const int t = blockIdx.x * 8 + wid;
    const int c0 = t * 8;
    if (c0 >= NN) return;

    uint32_t ah[2][4], al[2][4];
#pragma unroll
    for (int kc = 0; kc < 2; kc++) {
#pragma unroll
        for (int q = 0; q < 4; q++) {
            int r = (q & 1) ? gid + 8 : gid;
            int k = kc*8 + tig + ((q >> 1) ? 4 : 0);
            float f = (r < 12 && k < 12) ? W[r*12 + k] : 0.f;
            ah[kc][q] = f2tf32(f);
            al[kc][q] = f2tf32(f - __uint_as_float(ah[kc][q]));
        }
    }

    const float* inb = In + (size_t)b * Hh * NN;
    float acc[4] = {0.f, 0.f, 0.f, 0.f};

#pragma unroll
    for (int kc = 0; kc < 2; kc++) {
        int k0 = kc*8 + tig, k1 = kc*8 + tig + 4;
        int col = c0 + gid;
        float x0 = 0.f, x1 = 0.f;
        if (col < NN) {
            if (k0 < 12) x0 = inb[(size_t)k0*NN + col];
            if (k1 < 12) x1 = inb[(size_t)k1*NN + col];
        }
        uint32_t bh0 = f2tf32(x0), bh1 = f2tf32(x1);
        uint32_t bl0 = f2tf32(x0 - __uint_as_float(bh0));
        uint32_t bl1 = f2tf32(x1 - __uint_as_float(bh1));
        mma_tf32(acc, ah[kc][0], ah[kc][1], ah[kc][2], ah[kc][3], bh0, bh1);
        mma_tf32(acc, al[kc][0], al[kc][1], al[kc][2], al[kc][3], bh0, bh1);
        mma_tf32(acc, ah[kc][0], ah[kc][1], ah[kc][2], ah[kc][3], bl0, bl1);
    }

#pragma unroll
    for (int half = 0; half < 2; half++) {
        int r = gid + half*8;
        if (r >= 12) continue;
#pragma unroll
        for (int j = 0; j < 2; j++) {
            int c = c0 + 2*tig + j;
            if (c >= NN) continue;
            float val = acc[half*2 + j];
            if (mode == 0) {
                Out_ext[((size_t)(b*Hh + r))*NN + c] = val;
            } else {
                int n = c / Nn, m = c - n*Nn;
                g_attnW[(((size_t)(b*Hh + r))*Nn + n)*NNP + m] = __float2half_rn(val);
            }
        }
    }
}

// =====================================================================
extern "C" void kernel_launch(void* const* d_in, const int* in_sizes, int n_in,
                              void* d_out, int out_size)
{
    const float* x       = (const float*)d_in[0];
    const float* w_qkv   = (const float*)d_in[1];
    const float* w_proj  = (const float*)d_in[2];
    const float* b_proj  = (const float*)d_in[3];
    const float* w_convl = (const float*)d_in[4];
    const float* w_convw = (const float*)d_in[5];

    float* out0       = (float*)d_out;                       // attention_output [B,N,C]
    float* out_scores = out0 + (size_t)M1*Cc;                // [B,H,N,N]
    float* out_probs  = out_scores + (size_t)BH*NN;          // [B,H,N,N]
    float* out_vm     = out_probs  + (size_t)BH*NN;          // [B,H,N,N]

    const int conv_tiles  = (NN + 7) / 8;                    // 4852
    const int conv_blocks = (conv_tiles + 7) / 8;            // 607

    // 0) pre-convert inputs to half
    {
        int nx = (M1*Cc/8 + 255) / 256;
        k_cvt_x<<<nx, 256>>>(x);
        int nq = (3*Cc*(Cc/8) + 255) / 256;
        k_cvt_T<<<nq, 256>>>(w_qkv, 3*Cc, 0);
        int np = (Cc*(Cc/8) + 255) / 256;
        k_cvt_T<<<np, 256>>>(w_proj, Cc, 1);
    }

    // 1) QKV projection
    k_tgemm<<<dim3(18, 50), 256>>>(0, nullptr, nullptr);

    // 2) attention scores and raw scaled v v^T
    k_bgemm_f16<<<dim3(2, 2, BH), 256>>>(0, out_scores, SCALE);
    k_bgemm_f16<<<dim3(2, 2, BH), 256>>>(1, out_vm, SCALE);

    // 3) softmax -> value_map
    {
        int nrows = BH * Nn;
        int blocks = (nrows + 3) / 4;
        k_softmax_rows<<<blocks, 128>>>(out_vm, nrows);
    }

    // 4a) conv_l
    k_conv<<<dim3(conv_blocks, Bb), 256>>>(out_scores, w_convl, out_probs, 0);

    // 4b) softmax -> probs
    {
        int nrows = BH * Nn;
        int blocks = (nrows + 3) / 4;
        k_softmax_rows<<<blocks, 128>>>(out_probs, nrows);
    }

    // 4c) conv_w -> g_attnW
    k_conv<<<dim3(conv_blocks, Bb), 256>>>(out_probs, w_convw, nullptr, 1);

    // 5) attnW @ v
    k_av_f16<<<dim3(1, 2, BH), 256>>>();

    // 6) projection + bias
    k_tgemm<<<dim3(6, 50), 256>>>(1, b_proj, out0);
}

// round 16
// speedup vs baseline: 2.1615x; 1.0715x over previous
#include <cuda_runtime.h>
#include <cuda_fp16.h>
#include <cstdint>
#include <math.h>

#define Bb 32
#define Nn 197
#define Cc 768
#define Hh 12
#define Dd 64
#define NN (Nn*Nn)      // 38809
#define BH (Bb*Hh)      // 384
#define M1 (Bb*Nn)      // 6304
#define NNP 224         // padded attnW / vT row stride
#define SCALE 0.125f

// ---------------- scratch (no allocations allowed) ----------------
__device__ __half h_x[(size_t)M1*Cc];
__device__ __half h_wqkvT[(size_t)3*Cc*Cc];    // w_qkv^T  [2304][768]
__device__ __half h_wprojT[(size_t)Cc*Cc];     // w_proj^T [768][768]
__device__ __half g_q[(size_t)BH*Nn*Dd];       // [B,H,N,D]
__device__ __half g_k[(size_t)BH*Nn*Dd];
__device__ __half g_v[(size_t)BH*Nn*Dd];
__device__ __half g_vT[(size_t)BH*Dd*NNP];     // [B,H,D,m] padded (pads never read vs zero A)
__device__ __half g_attnW[(size_t)BH*Nn*NNP];  // padded rows (pads stay 0)
__device__ __half g_oh[(size_t)M1*Cc];

// ---------------- warp reductions ----------------
__device__ __forceinline__ float warpMax(float v){
#pragma unroll
    for (int o=16;o>0;o>>=1) v = fmaxf(v, __shfl_xor_sync(0xffffffffu, v, o));
    return v;
}
__device__ __forceinline__ float warpSum(float v){
#pragma unroll
    for (int o=16;o>0;o>>=1) v += __shfl_xor_sync(0xffffffffu, v, o);
    return v;
}

// ---------------- mma / async helpers ----------------
__device__ __forceinline__ uint32_t f2tf32(float x) {
    uint32_t u;
    asm("cvt.rna.tf32.f32 %0, %1;" : "=r"(u) : "f"(x));
    return u;
}
__device__ __forceinline__ void mma_tf32(float* d,
                                         uint32_t a0, uint32_t a1, uint32_t a2, uint32_t a3,
                                         uint32_t b0, uint32_t b1) {
    asm volatile(
        "mma.sync.aligned.m16n8k8.row.col.f32.tf32.tf32.f32 "
        "{%0,%1,%2,%3}, {%4,%5,%6,%7}, {%8,%9}, {%0,%1,%2,%3};"
        : "+f"(d[0]), "+f"(d[1]), "+f"(d[2]), "+f"(d[3])
        : "r"(a0), "r"(a1), "r"(a2), "r"(a3), "r"(b0), "r"(b1));
}
__device__ __forceinline__ void mma_f16(float* d,
                                        uint32_t a0, uint32_t a1, uint32_t a2, uint32_t a3,
                                        uint32_t b0, uint32_t b1) {
    asm volatile(
        "mma.sync.aligned.m16n8k16.row.col.f32.f16.f16.f32 "
        "{%0,%1,%2,%3}, {%4,%5,%6,%7}, {%8,%9}, {%0,%1,%2,%3};"
        : "+f"(d[0]), "+f"(d[1]), "+f"(d[2]), "+f"(d[3])
        : "r"(a0), "r"(a1), "r"(a2), "r"(a3), "r"(b0), "r"(b1));
}
__device__ __forceinline__ void ldsm_x4(uint32_t& r0, uint32_t& r1,
                                        uint32_t& r2, uint32_t& r3, uint32_t addr) {
    asm volatile("ldmatrix.sync.aligned.m8n8.x4.shared.b16 {%0,%1,%2,%3}, [%4];"
                 : "=r"(r0), "=r"(r1), "=r"(r2), "=r"(r3) : "r"(addr));
}
__device__ __forceinline__ void cp16(uint32_t dst, const void* src, bool p) {
    int sz = p ? 16 : 0;
    asm volatile("cp.async.cg.shared.global [%0], [%1], 16, %2;"
                 :: "r"(dst), "l"(src), "r"(sz) : "memory");
}
#define CP_COMMIT() asm volatile("cp.async.commit_group;" ::: "memory")
#define CP_WAIT1()  asm volatile("cp.async.wait_group 1;" ::: "memory")

#define HS 40                     // smem row stride in halfs (32 + pad 8)

// =====================================================================
// P0: pre-convert x -> h_x
// =====================================================================
__global__ __launch_bounds__(256) void k_cvt_x(const float* __restrict__ X)
{
    size_t i = (size_t)(blockIdx.x * blockDim.x + threadIdx.x) * 8;
    if (i >= (size_t)M1*Cc) return;
    float4 a = *(const float4*)&X[i];
    float4 b = *(const float4*)&X[i + 4];
    __half2 h[4];
    h[0] = __floats2half2_rn(a.x, a.y);
    h[1] = __floats2half2_rn(a.z, a.w);
    h[2] = __floats2half2_rn(b.x, b.y);
    h[3] = __floats2half2_rn(b.z, b.w);
    *(uint4*)&h_x[i] = *(uint4*)h;
}

// =====================================================================
// P1: pre-convert + transpose weights: W[K,N] float -> WT[N,K] half
// =====================================================================
__global__ __launch_bounds__(256) void k_cvt_T(const float* __restrict__ W,
                                               int Nw, int mode)
{
    int idx = blockIdx.x * blockDim.x + threadIdx.x;
    int kg = idx % (Cc/8), n = idx / (Cc/8);
    if (n >= Nw) return;
    int k0 = kg * 8;
    __half2 h[4];
#pragma unroll
    for (int i = 0; i < 4; i++) {
        float f0 = W[(size_t)(k0 + 2*i    )*Nw + n];
        float f1 = W[(size_t)(k0 + 2*i + 1)*Nw + n];
        h[i] = __floats2half2_rn(f0, f1);
    }
    __half* out = (mode == 0) ? h_wqkvT : h_wprojT;
    *(uint4*)&out[(size_t)n*Cc + k0] = *(uint4*)h;
}

// =====================================================================
// K1/K6: dense GEMM, cp.async 2-deep pipeline + ldmatrix + fp16 mma.
// C = A[M,768] @ BT[N,768]^T. block 128x128, chunk 32, 8 warps (2m x 4n).
// =====================================================================
__global__ __launch_bounds__(256) void k_tgemm(int mode,
                                               const float* __restrict__ bias,
                                               float* __restrict__ out)
{
    __shared__ __align__(16) __half shA[2][128*HS];
    __shared__ __align__(16) __half shB[2][128*HS];

    const __half* A  = (mode == 1) ? g_oh : h_x;
    const __half* BT = (mode == 1) ? h_wprojT : h_wqkvT;

    const int tid  = threadIdx.x;
    const int wid  = tid >> 5, lane = tid & 31;
    const int gid  = lane >> 2, tig = lane & 3;
    const int warp_m = (wid >> 2) * 64;
    const int warp_n = (wid & 3) * 32;
    const int row0 = blockIdx.y * 128;
    const int col0 = blockIdx.x * 128;

    const uint32_t aB0 = (uint32_t)__cvta_generic_to_shared(shA[0]);
    const uint32_t aB1 = (uint32_t)__cvta_generic_to_shared(shA[1]);
    const uint32_t bB0 = (uint32_t)__cvta_generic_to_shared(shB[0]);
    const uint32_t bB1 = (uint32_t)__cvta_generic_to_shared(shB[1]);

    const int aRow = warp_m + (lane & 15);
    const int aKh  = ((lane >> 4) & 1) * 8;
    const int bG   = lane >> 3;
    const int bCol = warp_n + ((bG >> 1) * 8) + (lane & 7);
    const int bKh  = (bG & 1) * 8;

    // per-thread staging coords (2 A rows, 2 B rows per chunk)
    const int sr0 = tid >> 2,        sk8 = (tid & 3) * 8;   // e = tid
    const int sr1 = (256 + tid) >> 2;                        // e = 256+tid, same k8

    float acc[4][4][4] = {};

    auto stage = [&](int c, int buf) {
        const int k0 = c << 5;
        uint32_t ab = buf ? aB1 : aB0;
        uint32_t bb = buf ? bB1 : bB0;
        cp16(ab + (sr0*HS + sk8)*2, &A[(size_t)(row0 + sr0)*Cc + k0 + sk8], row0 + sr0 < M1);
        cp16(ab + (sr1*HS + sk8)*2, &A[(size_t)(row0 + sr1)*Cc + k0 + sk8], row0 + sr1 < M1);
        cp16(bb + (sr0*HS + sk8)*2, &BT[(size_t)(col0 + sr0)*Cc + k0 + sk8], true);
        cp16(bb + (sr1*HS + sk8)*2, &BT[(size_t)(col0 + sr1)*Cc + k0 + sk8], true);
    };

    stage(0, 0); CP_COMMIT();
    stage(1, 1); CP_COMMIT();

    for (int c = 0; c < 24; c++) {
        const int buf = c & 1;
        CP_WAIT1();
        __syncthreads();
        const uint32_t ab = buf ? aB1 : aB0;
        const uint32_t bb = buf ? bB1 : bB0;
#pragma unroll
        for (int ks = 0; ks < 2; ks++) {
            const int kk = ks * 16;
            uint32_t ah[4][4];
#pragma unroll
            for (int ma = 0; ma < 4; ma++) {
                uint32_t addr = ab + (uint32_t)(((aRow + ma*16)*HS + kk + aKh) * 2);
                ldsm_x4(ah[ma][0], ah[ma][1], ah[ma][2], ah[ma][3], addr);
            }
            uint32_t bf[4][2];
#pragma unroll
            for (int p = 0; p < 2; p++) {
                uint32_t addr = bb + (uint32_t)(((bCol + p*16)*HS + kk + bKh) * 2);
                uint32_t r0, r1, r2, r3;
                ldsm_x4(r0, r1, r2, r3, addr);
                bf[p*2  ][0] = r0; bf[p*2  ][1] = r1;
                bf[p*2+1][0] = r2; bf[p*2+1][1] = r3;
            }
#pragma unroll
            for (int na = 0; na < 4; na++)
#pragma unroll
                for (int ma = 0; ma < 4; ma++)
                    mma_f16(acc[ma][na], ah[ma][0], ah[ma][1], ah[ma][2], ah[ma][3],
                            bf[na][0], bf[na][1]);
        }
        __syncthreads();
        if (c + 2 < 24) stage(c + 2, buf);
        CP_COMMIT();
    }

#pragma unroll
    for (int ma = 0; ma < 4; ma++) {
#pragma unroll
        for (int na = 0; na < 4; na++) {
            int colg = col0 + warp_n + na*8 + 2*tig;
#pragma unroll
            for (int half = 0; half < 2; half++) {
                int row = row0 + warp_m + ma*16 + gid + half*8;
                if (row >= M1) continue;
                float v0 = acc[ma][na][half*2 + 0];
                float v1 = acc[ma][na][half*2 + 1];
                if (mode == 0) {
                    int t = colg / 768;
                    int rem = colg - t*768;
                    int h = rem >> 6, d0 = rem & 63;
                    __half* dst = (t==0) ? g_q : (t==1) ? g_k : g_v;
                    int b = row / Nn, n = row - b*Nn;
                    size_t z = (size_t)(b*Hh + h);
                    *(__half2*)&dst[(z*Nn + n)*Dd + d0] = __floats2half2_rn(v0, v1);
                    if (t == 2) {   // also transposed copy for k_av staging
                        g_vT[(z*Dd + d0    )*NNP + n] = __float2half_rn(v0);
                        g_vT[(z*Dd + d0 + 1)*NNP + n] = __float2half_rn(v1);
                    }
                } else {
                    float* p = out + (size_t)row*768 + colg;
                    p[0] = v0 + bias[colg];
                    p[1] = v1 + bias[colg + 1];
                }
            }
        }
    }
}

// =====================================================================
// K2: batched NT GEMM, cp.async pipeline: out[z,n,m] = alpha*sum A*B
// block 128x128, K=64 (2 chunks), 8 warps (2m x 4n).
// =====================================================================
__global__ __launch_bounds__(256) void k_bgemm_f16(int mode,
                                                   float* __restrict__ out,
                                                   float alpha)
{
    __shared__ __align__(16) __half shA[2][128*HS];
    __shared__ __align__(16) __half shB[2][128*HS];

    const int z = blockIdx.z;
    const __half* Az = (mode==0 ? g_q : g_v) + (size_t)z*Nn*Dd;
    const __half* Bz = (mode==0 ? g_k : g_v) + (size_t)z*Nn*Dd;
    float* Oz = out + (size_t)z*NN;

    const int tid  = threadIdx.x;
    const int wid  = tid >> 5, lane = tid & 31;
    const int gid  = lane >> 2, tig = lane & 3;
    const int warp_m = (wid >> 2) * 64;
    const int warp_n = (wid & 3) * 32;
    const int n0 = blockIdx.y * 128;
    const int m0 = blockIdx.x * 128;

    const uint32_t aB0 = (uint32_t)__cvta_generic_to_shared(shA[0]);
    const uint32_t aB1 = (uint32_t)__cvta_generic_to_shared(shA[1]);
    const uint32_t bB0 = (uint32_t)__cvta_generic_to_shared(shB[0]);
    const uint32_t bB1 = (uint32_t)__cvta_generic_to_shared(shB[1]);

    const int aRow = warp_m + (lane & 15);
    const int aKh  = ((lane >> 4) & 1) * 8;
    const int bG   = lane >> 3;
    const int bCol = warp_n + ((bG >> 1) * 8) + (lane & 7);
    const int bKh  = (bG & 1) * 8;

    const int sr0 = tid >> 2, sk8 = (tid & 3) * 8;
    const int sr1 = (256 + tid) >> 2;

    float acc[4][4][4] = {};

    auto stage = [&](int c, int buf) {
        const int k0 = c << 5;
        uint32_t ab = buf ? aB1 : aB0;
        uint32_t bb = buf ? bB1 : bB0;
        cp16(ab + (sr0*HS + sk8)*2, &Az[(size_t)(n0 + sr0)*Dd + k0 + sk8], n0 + sr0 < Nn);
        cp16(ab + (sr1*HS + sk8)*2, &Az[(size_t)(n0 + sr1)*Dd + k0 + sk8], n0 + sr1 < Nn);
        cp16(bb + (sr0*HS + sk8)*2, &Bz[(size_t)(m0 + sr0)*Dd + k0 + sk8], m0 + sr0 < Nn);
        cp16(bb + (sr1*HS + sk8)*2, &Bz[(size_t)(m0 + sr1)*Dd + k0 + sk8], m0 + sr1 < Nn);
    };

    stage(0, 0); CP_COMMIT();
    stage(1, 1); CP_COMMIT();

#pragma unroll
    for (int c = 0; c < 2; c++) {
        const int buf = c & 1;
        CP_WAIT1();
        __syncthreads();
        const uint32_t ab = buf ? aB1 : aB0;
        const uint32_t bb = buf ? bB1 : bB0;
#pragma unroll
        for (int ks = 0; ks < 2; ks++) {
            const int kk = ks * 16;
            uint32_t ah[4][4];
#pragma unroll
            for (int ma = 0; ma < 4; ma++) {
                uint32_t addr = ab + (uint32_t)(((aRow + ma*16)*HS + kk + aKh) * 2);
                ldsm_x4(ah[ma][0], ah[ma][1], ah[ma][2], ah[ma][3], addr);
            }
            uint32_t bf[4][2];
#pragma unroll
            for (int p = 0; p < 2; p++) {
                uint32_t addr = bb + (uint32_t)(((bCol + p*16)*HS + kk + bKh) * 2);
                uint32_t r0, r1, r2, r3;
                ldsm_x4(r0, r1, r2, r3, addr);
                bf[p*2  ][0] = r0; bf[p*2  ][1] = r1;
                bf[p*2+1][0] = r2; bf[p*2+1][1] = r3;
            }
#pragma unroll
            for (int na = 0; na < 4; na++)
#pragma unroll
                for (int ma = 0; ma < 4; ma++)
                    mma_f16(acc[ma][na], ah[ma][0], ah[ma][1], ah[ma][2], ah[ma][3],
                            bf[na][0], bf[na][1]);
        }
        __syncthreads();
        CP_COMMIT();
    }

#pragma unroll
    for (int ma = 0; ma < 4; ma++) {
#pragma unroll
        for (int na = 0; na < 4; na++) {
            int mg = m0 + warp_n + na*8 + 2*tig;
#pragma unroll
            for (int half = 0; half < 2; half++) {
                int n = n0 + warp_m + ma*16 + gid + half*8;
                if (n >= Nn) continue;
                if (mg < Nn)     Oz[(size_t)n*Nn + mg]     = alpha*acc[ma][na][half*2+0];
                if (mg + 1 < Nn) Oz[(size_t)n*Nn + mg + 1] = alpha*acc[ma][na][half*2+1];
            }
        }
    }
}

// =====================================================================
// K5: av, cp.async pipeline: out[n,d] = sum_m attnW[n,m] * v[m,d]
// A = attnW padded; B = g_vT[d][m] padded (junk pads ok: A pads are 0).
// block 128x64, 7 chunks of 32, 8 warps (4m x 2n).
// =====================================================================
__global__ __launch_bounds__(256) void k_av_f16()
{
    __shared__ __align__(16) __half shA[2][128*HS];   // [n][k]
    __shared__ __align__(16) __half shB[2][64*HS];    // [d][k]

    const int z = blockIdx.z;
    const int b = z / Hh, h = z - b*Hh;
    const __half* Az = g_attnW + (size_t)z*Nn*NNP;
    const __half* VT = g_vT + (size_t)z*Dd*NNP;

    const int tid  = threadIdx.x;
    const int wid  = tid >> 5, lane = tid & 31;
    const int gid  = lane >> 2, tig = lane & 3;
    const int warp_m = (wid >> 1) * 32;
    const int warp_n = (wid & 1) * 32;
    const int n0 = blockIdx.y * 128;

    const uint32_t aB0 = (uint32_t)__cvta_generic_to_shared(shA[0]);
    const uint32_t aB1 = (uint32_t)__cvta_generic_to_shared(shA[1]);
    const uint32_t bB0 = (uint32_t)__cvta_generic_to_shared(shB[0]);
    const uint32_t bB1 = (uint32_t)__cvta_generic_to_shared(shB[1]);

    const int aRow = warp_m + (lane & 15);
    const int aKh  = ((lane >> 4) & 1) * 8;
    const int bG   = lane >> 3;
    const int bCol = warp_n + ((bG >> 1) * 8) + (lane & 7);
    const int bKh  = (bG & 1) * 8;

    const int sr0 = tid >> 2, sk8 = (tid & 3) * 8;
    const int sr1 = (256 + tid) >> 2;

    float acc[2][4][4] = {};

    auto stage = [&](int c, int buf) {
        const int k0 = c << 5;
        uint32_t ab = buf ? aB1 : aB0;
        uint32_t bb = buf ? bB1 : bB0;
        cp16(ab + (sr0*HS + sk8)*2, &Az[(size_t)(n0 + sr0)*NNP + k0 + sk8], n0 + sr0 < Nn);
        cp16(ab + (sr1*HS + sk8)*2, &Az[(size_t)(n0 + sr1)*NNP + k0 + sk8], n0 + sr1 < Nn);
        // B: 64 rows x 32k = 256 uint4, 1 per thread
        cp16(bb + (sr0*HS + sk8)*2, &VT[(size_t)sr0*NNP + k0 + sk8], sr0 < 64);
    };

    stage(0, 0); CP_COMMIT();
    stage(1, 1); CP_COMMIT();

#pragma unroll 1
    for (int c = 0; c < 7; c++) {
        const int buf = c & 1;
        CP_WAIT1();
        __syncthreads();
        const uint32_t ab = buf ? aB1 : aB0;
        const uint32_t bb = buf ? bB1 : bB0;
#pragma unroll
        for (int ks = 0; ks < 2; ks++) {
            const int kk = ks * 16;
            uint32_t ah[2][4];
#pragma unroll
            for (int ma = 0; ma < 2; ma++) {
                uint32_t addr = ab + (uint32_t)(((aRow + ma*16)*HS + kk + aKh) * 2);
                ldsm_x4(ah[ma][0], ah[ma][1], ah[ma][2], ah[ma][3], addr);
            }
            uint32_t bf[4][2];
#pragma unroll
            for (int p = 0; p < 2; p++) {
                uint32_t addr = bb + (uint32_t)(((bCol + p*16)*HS + kk + bKh) * 2);
                uint32_t r0, r1, r2, r3;
                ldsm_x4(r0, r1, r2, r3, addr);
                bf[p*2  ][0] = r0; bf[p*2  ][1] = r1;
                bf[p*2+1][0] = r2; bf[p*2+1][1] = r3;
            }
#pragma unroll
            for (int na = 0; na < 4; na++)
#pragma unroll
                for (int ma = 0; ma < 2; ma++)
                    mma_f16(acc[ma][na], ah[ma][0], ah[ma][1], ah[ma][2], ah[ma][3],
                            bf[na][0], bf[na][1]);
        }
        __syncthreads();
        if (c + 2 < 7) stage(c + 2, buf);
        CP_COMMIT();
    }

#pragma unroll
    for (int ma = 0; ma < 2; ma++) {
#pragma unroll
        for (int na = 0; na < 4; na++) {
            int colg = warp_n + na*8 + 2*tig;
#pragma unroll
            for (int half = 0; half < 2; half++) {
                int n = n0 + warp_m + ma*16 + gid + half*8;
                if (n >= Nn) continue;
                *(__half2*)&g_oh[((size_t)(b*Nn + n))*Cc + h*Dd + colg] =
                    __floats2half2_rn(acc[ma][na][half*2 + 0], acc[ma][na][half*2 + 1]);
            }
        }
    }
}

// =====================================================================
// K3: in-place row softmax, one warp per row of length 197
// =====================================================================
__global__ __launch_bounds__(128) void k_softmax_rows(float* __restrict__ data,
                                                      int nrows)
{
    int warp = (blockIdx.x * blockDim.x + threadIdx.x) >> 5;
    int lane = threadIdx.x & 31;
    if (warp >= nrows) return;
    float* row = data + (size_t)warp * Nn;
    float v[7];
    float mx = -INFINITY;
#pragma unroll
    for (int i=0;i<7;i++) {
        int m = lane + i*32;
        v[i] = (m < Nn) ? row[m] : -INFINITY;
        mx = fmaxf(mx, v[i]);
    }
    mx = warpMax(mx);
    float s = 0.f;
#pragma unroll
    for (int i=0;i<7;i++) {
        int m = lane + i*32;
        v[i] = (m < Nn) ? __expf(v[i]-mx) : 0.f;
        s += v[i];
    }
    s = warpSum(s);
    float inv = 1.f / s;
#pragma unroll
    for (int i=0;i<7;i++) {
        int m = lane + i*32;
        if (m < Nn) row[m] = v[i]*inv;
    }
}

// =====================================================================
// K4: head-mix conv as flat GEMM per batch (tf32 3-term split)
// mode 0: scores -> probs logits (float). mode 1: probs -> g_attnW (half).
// =====================================================================
__global__ __launch_bounds__(256) void k_conv(const float* __restrict__ In,
                                              const float* __restrict__ W,
                                              float* __restrict__ Out_ext,
                                              int mode)
{
    const int b = blockIdx.y;
    const int wid = (threadIdx.x) >> 5, lane = threadIdx.x & 31;
    const int gid = lane >> 2, tig = lane & 3;
    const int t = blockIdx.x * 8 + wid;
    const int c0 = t * 8;
    if (c0 >= NN) return;

    uint32_t ah[2][4], al[2][4];
#pragma unroll
    for (int kc = 0; kc < 2; kc++) {
#pragma unroll
        for (int q = 0; q < 4; q++) {
            int r = (q & 1) ? gid + 8 : gid;
            int k = kc*8 + tig + ((q >> 1) ? 4 : 0);
            float f = (r < 12 && k < 12) ? W[r*12 + k] : 0.f;
            ah[kc][q] = f2tf32(f);
            al[kc][q] = f2tf32(f - __uint_as_float(ah[kc][q]));
        }
    }

    const float* inb = In + (size_t)b * Hh * NN;
    float acc[4] = {0.f, 0.f, 0.f, 0.f};

#pragma unroll
    for (int kc = 0; kc < 2; kc++) {
        int k0 = kc*8 + tig, k1 = kc*8 + tig + 4;
        int col = c0 + gid;
        float x0 = 0.f, x1 = 0.f;
        if (col < NN) {
            if (k0 < 12) x0 = inb[(size_t)k0*NN + col];
            if (k1 < 12) x1 = inb[(size_t)k1*NN + col];
        }
        uint32_t bh0 = f2tf32(x0), bh1 = f2tf32(x1);
        uint32_t bl0 = f2tf32(x0 - __uint_as_float(bh0));
        uint32_t bl1 = f2tf32(x1 - __uint_as_float(bh1));
        mma_tf32(acc, ah[kc][0], ah[kc][1], ah[kc][2], ah[kc][3], bh0, bh1);
        mma_tf32(acc, al[kc][0], al[kc][1], al[kc][2], al[kc][3], bh0, bh1);
        mma_tf32(acc, ah[kc][0], ah[kc][1], ah[kc][2], ah[kc][3], bl0, bl1);
    }

#pragma unroll
    for (int half = 0; half < 2; half++) {
        int r = gid + half*8;
        if (r >= 12) continue;
#pragma unroll
        for (int j = 0; j < 2; j++) {
            int c = c0 + 2*tig + j;
            if (c >= NN) continue;
            float val = acc[half*2 + j];
            if (mode == 0) {
                Out_ext[((size_t)(b*Hh + r))*NN + c] = val;
            } else {
                int n = c / Nn, m = c - n*Nn;
                g_attnW[(((size_t)(b*Hh + r))*Nn + n)*NNP + m] = __float2half_rn(val);
            }
        }
    }
}

// =====================================================================
extern "C" void kernel_launch(void* const* d_in, const int* in_sizes, int n_in,
                              void* d_out, int out_size)
{
    const float* x       = (const float*)d_in[0];
    const float* w_qkv   = (const float*)d_in[1];
    const float* w_proj  = (const float*)d_in[2];
    const float* b_proj  = (const float*)d_in[3];
    const float* w_convl = (const float*)d_in[4];
    const float* w_convw = (const float*)d_in[5];

    float* out0       = (float*)d_out;                       // attention_output [B,N,C]
    float* out_scores = out0 + (size_t)M1*Cc;                // [B,H,N,N]
    float* out_probs  = out_scores + (size_t)BH*NN;          // [B,H,N,N]
    float* out_vm     = out_probs  + (size_t)BH*NN;          // [B,H,N,N]

    const int conv_tiles  = (NN + 7) / 8;                    // 4852
    const int conv_blocks = (conv_tiles + 7) / 8;            // 607

    // 0) pre-convert inputs to half
    {
        int nx = (M1*Cc/8 + 255) / 256;
        k_cvt_x<<<nx, 256>>>(x);
        int nq = (3*Cc*(Cc/8) + 255) / 256;
        k_cvt_T<<<nq, 256>>>(w_qkv, 3*Cc, 0);
        int np = (Cc*(Cc/8) + 255) / 256;
        k_cvt_T<<<np, 256>>>(w_proj, Cc, 1);
    }

    // 1) QKV projection (also writes g_vT)
    k_tgemm<<<dim3(18, 50), 256>>>(0, nullptr, nullptr);

    // 2) attention scores and raw scaled v v^T
    k_bgemm_f16<<<dim3(2, 2, BH), 256>>>(0, out_scores, SCALE);
    k_bgemm_f16<<<dim3(2, 2, BH), 256>>>(1, out_vm, SCALE);

    // 3) softmax -> value_map
    {
        int nrows = BH * Nn;
        int blocks = (nrows + 3) / 4;
        k_softmax_rows<<<blocks, 128>>>(out_vm, nrows);
    }

    // 4a) conv_l
    k_conv<<<dim3(conv_blocks, Bb), 256>>>(out_scores, w_convl, out_probs, 0);

    // 4b) softmax -> probs
    {
        int nrows = BH * Nn;
        int blocks = (nrows + 3) / 4;
        k_softmax_rows<<<blocks, 128>>>(out_probs, nrows);
    }

    // 4c) conv_w -> g_attnW
    k_conv<<<dim3(conv_blocks, Bb), 256>>>(out_probs, w_convw, nullptr, 1);

    // 5) attnW @ v
    k_av_f16<<<dim3(1, 2, BH), 256>>>();

    // 6) projection + bias
    k_tgemm<<<dim3(6, 50), 256>>>(1, b_proj, out0);
}